// round 5
// baseline (speedup 1.0000x reference)
#include <cuda_runtime.h>
#include <cuda_bf16.h>
#include <cstddef>

// ---------------------------------------------------------------------------
// SpatialAttention: out = relu( MHA( relu(H@Wq+bq), relu(H@Wk+bk), relu(H@Wv+bv) ) @ Wo + bo )
// H = concat(X[...,128], STE[...,256]) -> [49152, 384]
// B=8, T=12, N=512, D_MODEL=128, K_HEADS=8, D_HEAD=16
// ---------------------------------------------------------------------------

#define NTOK   49152      // B*T*N
#define BT     96         // B*T
#define SEQ    512        // N
#define DM     128        // D_MODEL
#define DH     16         // D_HEAD
#define NH     8          // heads
#define KDIM   384        // 3*DM

// Scratch (head-major q/k/v for attention; token-major attn output for final GEMM)
__device__ float g_q[BT * NH * SEQ * DH];     // 6.29M floats
__device__ float g_k[BT * NH * SEQ * DH];
__device__ float g_v[BT * NH * SEQ * DH];
__device__ float g_attn[NTOK * DM];           // 6.29M floats

// ---------------------------------------------------------------------------
// Kernel 1: QKV projection. C[m, j] = relu(sum_k H[m,k] * W[k,j] + b[j])
// Tiled fp32 GEMM: BM=128, BN=128(one weight matrix per n-block), BK=8
// grid = (384 m-blocks, 3 matrices), 256 threads, 8x8 micro-tile.
// Output scattered head-major into g_q/g_k/g_v.
// ---------------------------------------------------------------------------
#define BM 128
#define BN 128
#define BK 8
#define APITCH (BM + 8)   // 136, multiple of 4 -> float4-aligned rows

__global__ void __launch_bounds__(256, 2)
qkv_kernel(const float* __restrict__ X, const float* __restrict__ STE,
           const float* __restrict__ Wq, const float* __restrict__ Wk,
           const float* __restrict__ Wv,
           const float* __restrict__ bq, const float* __restrict__ bk,
           const float* __restrict__ bv)
{
    __shared__ __align__(16) float As[BK][APITCH];
    __shared__ __align__(16) float Bs[BK][BN];

    const int mblk = blockIdx.x;
    const int nsel = blockIdx.y;        // 0=q, 1=k, 2=v
    const float* W    = (nsel == 0) ? Wq : (nsel == 1) ? Wk : Wv;
    const float* bias = (nsel == 0) ? bq : (nsel == 1) ? bk : bv;
    float* out        = (nsel == 0) ? g_q : (nsel == 1) ? g_k : g_v;

    const int tid = threadIdx.x;
    const int tx = tid & 15;            // 16 n-groups
    const int ty = tid >> 4;            // 16 m-groups
    const int m0 = mblk * BM;

    // A loader: thread -> (row ra, 4 consecutive cols at ca)
    const int ra = tid >> 1;            // 0..127
    const int ca = (tid & 1) * 4;       // 0 or 4
    // B loader: thread -> (row rb, 4 consecutive cols at cb)
    const int rb = tid >> 5;            // 0..7
    const int cb = (tid & 31) * 4;      // 0..124

    float acc[8][8];
    #pragma unroll
    for (int i = 0; i < 8; i++)
        #pragma unroll
        for (int j = 0; j < 8; j++) acc[i][j] = 0.f;

    const int NT = KDIM / BK;           // 48

    // prefetch tile 0
    float4 pa, pb;
    {
        int k = ca;  // kt=0
        const float* src = (k < DM) ? (X + (size_t)(m0 + ra) * DM + k)
                                    : (STE + (size_t)(m0 + ra) * 256 + (k - DM));
        pa = *(const float4*)src;
        pb = *(const float4*)(W + (size_t)rb * DM + cb);
    }

    for (int kt = 0; kt < NT; ++kt) {
        // stage
        As[ca + 0][ra] = pa.x;
        As[ca + 1][ra] = pa.y;
        As[ca + 2][ra] = pa.z;
        As[ca + 3][ra] = pa.w;
        *(float4*)&Bs[rb][cb] = pb;
        __syncthreads();

        if (kt + 1 < NT) {
            int k = (kt + 1) * BK + ca;
            const float* src = (k < DM) ? (X + (size_t)(m0 + ra) * DM + k)
                                        : (STE + (size_t)(m0 + ra) * 256 + (k - DM));
            pa = *(const float4*)src;
            pb = *(const float4*)(W + (size_t)((kt + 1) * BK + rb) * DM + cb);
        }

        #pragma unroll
        for (int kk = 0; kk < BK; kk++) {
            float a[8], b[8];
            *(float4*)(a)     = *(const float4*)&As[kk][ty * 8];
            *(float4*)(a + 4) = *(const float4*)&As[kk][ty * 8 + 4];
            *(float4*)(b)     = *(const float4*)&Bs[kk][tx * 8];
            *(float4*)(b + 4) = *(const float4*)&Bs[kk][tx * 8 + 4];
            #pragma unroll
            for (int i = 0; i < 8; i++)
                #pragma unroll
                for (int j = 0; j < 8; j++)
                    acc[i][j] = fmaf(a[i], b[j], acc[i][j]);
        }
        __syncthreads();
    }

    // epilogue: relu(acc + bias), scatter head-major: [(bt*8+h)*512 + n]*16 + d
    #pragma unroll
    for (int i = 0; i < 8; i++) {
        int m = m0 + ty * 8 + i;
        int bt = m >> 9;
        int n  = m & 511;
        #pragma unroll
        for (int j = 0; j < 8; j += 4) {
            int c = tx * 8 + j;          // 0..127, stays within one head (c%16 in {0,8})
            int h = c >> 4;
            int d = c & 15;
            float4 r;
            r.x = fmaxf(acc[i][j + 0] + bias[c + 0], 0.f);
            r.y = fmaxf(acc[i][j + 1] + bias[c + 1], 0.f);
            r.z = fmaxf(acc[i][j + 2] + bias[c + 2], 0.f);
            r.w = fmaxf(acc[i][j + 3] + bias[c + 3], 0.f);
            *(float4*)&out[((size_t)(bt * NH + h) * SEQ + n) * DH + d] = r;
        }
    }
}

// ---------------------------------------------------------------------------
// Kernel 2: attention per (bt, head). 768 blocks x 256 threads.
// Each thread owns 2 query rows; K/V streamed through smem in 2 chunks of 256.
// Softmax WITHOUT running max: scores s = q.k/4 are bounded (|s| << 80), so
// p = exp(s - 8) cannot overflow; the -8 shift cancels exactly in the ratio.
// ---------------------------------------------------------------------------
#define CHUNK 256

__global__ void __launch_bounds__(256, 2)
attn_kernel()
{
    __shared__ __align__(16) float sk[CHUNK * DH];
    __shared__ __align__(16) float sv[CHUNK * DH];

    const int bth = blockIdx.x;              // bt*8 + h
    const size_t base = (size_t)bth * (SEQ * DH);
    const int tid = threadIdx.x;

    float q0[DH], q1[DH];
    {
        const float4* qp0 = (const float4*)(g_q + base + (size_t)tid * DH);
        const float4* qp1 = (const float4*)(g_q + base + (size_t)(tid + 256) * DH);
        #pragma unroll
        for (int j = 0; j < 4; j++) { ((float4*)q0)[j] = qp0[j]; ((float4*)q1)[j] = qp1[j]; }
    }

    float o0[DH], o1[DH];
    #pragma unroll
    for (int d = 0; d < DH; d++) { o0[d] = 0.f; o1[d] = 0.f; }
    float L0 = 0.f, L1 = 0.f;

    for (int ch = 0; ch < SEQ / CHUNK; ++ch) {
        const float4* kp = (const float4*)(g_k + base + (size_t)ch * CHUNK * DH);
        const float4* vp = (const float4*)(g_v + base + (size_t)ch * CHUNK * DH);
        #pragma unroll
        for (int j = 0; j < 4; j++) {
            ((float4*)sk)[tid + j * 256] = kp[tid + j * 256];
            ((float4*)sv)[tid + j * 256] = vp[tid + j * 256];
        }
        __syncthreads();

        for (int m = 0; m < CHUNK; m++) {
            float kr[DH];
            #pragma unroll
            for (int j = 0; j < 4; j++) ((float4*)kr)[j] = ((const float4*)sk)[m * 4 + j];

            float s0a = 0.f, s0b = 0.f, s1a = 0.f, s1b = 0.f;
            #pragma unroll
            for (int d = 0; d < DH; d += 2) {
                s0a = fmaf(q0[d],     kr[d],     s0a);
                s0b = fmaf(q0[d + 1], kr[d + 1], s0b);
                s1a = fmaf(q1[d],     kr[d],     s1a);
                s1b = fmaf(q1[d + 1], kr[d + 1], s1b);
            }
            float p0 = __expf(fmaf(s0a + s0b, 0.25f, -8.0f));
            float p1 = __expf(fmaf(s1a + s1b, 0.25f, -8.0f));
            L0 += p0;
            L1 += p1;

            float vr[DH];
            #pragma unroll
            for (int j = 0; j < 4; j++) ((float4*)vr)[j] = ((const float4*)sv)[m * 4 + j];
            #pragma unroll
            for (int d = 0; d < DH; d++) {
                o0[d] = fmaf(p0, vr[d], o0[d]);
                o1[d] = fmaf(p1, vr[d], o1[d]);
            }
        }
        __syncthreads();
    }

    const float inv0 = 1.f / L0;
    const float inv1 = 1.f / L1;
    const int bt = bth >> 3;
    const int h  = bth & 7;
    float* dst0 = g_attn + ((size_t)(bt * SEQ + tid)       * DM + h * DH);
    float* dst1 = g_attn + ((size_t)(bt * SEQ + tid + 256) * DM + h * DH);
    #pragma unroll
    for (int j = 0; j < 4; j++) {
        float4 r0, r1;
        r0.x = o0[j * 4 + 0] * inv0; r0.y = o0[j * 4 + 1] * inv0;
        r0.z = o0[j * 4 + 2] * inv0; r0.w = o0[j * 4 + 3] * inv0;
        r1.x = o1[j * 4 + 0] * inv1; r1.y = o1[j * 4 + 1] * inv1;
        r1.z = o1[j * 4 + 2] * inv1; r1.w = o1[j * 4 + 3] * inv1;
        *(float4*)(dst0 + j * 4) = r0;
        *(float4*)(dst1 + j * 4) = r1;
    }
}

// ---------------------------------------------------------------------------
// Kernel 3: output projection. out = relu(g_attn @ Wo + bo)
// M=49152, N=128, K=128. Same tiling as K1. grid = 384 blocks.
// ---------------------------------------------------------------------------
__global__ void __launch_bounds__(256, 2)
out_kernel(const float* __restrict__ Wo, const float* __restrict__ bo,
           float* __restrict__ out)
{
    __shared__ __align__(16) float As[BK][APITCH];
    __shared__ __align__(16) float Bs[BK][BN];

    const int mblk = blockIdx.x;
    const int tid = threadIdx.x;
    const int tx = tid & 15;
    const int ty = tid >> 4;
    const int m0 = mblk * BM;

    const int ra = tid >> 1;
    const int ca = (tid & 1) * 4;
    const int rb = tid >> 5;
    const int cb = (tid & 31) * 4;

    float acc[8][8];
    #pragma unroll
    for (int i = 0; i < 8; i++)
        #pragma unroll
        for (int j = 0; j < 8; j++) acc[i][j] = 0.f;

    const int NT = DM / BK;  // 16

    float4 pa = *(const float4*)(g_attn + (size_t)(m0 + ra) * DM + ca);
    float4 pb = *(const float4*)(Wo + (size_t)rb * DM + cb);

    for (int kt = 0; kt < NT; ++kt) {
        As[ca + 0][ra] = pa.x;
        As[ca + 1][ra] = pa.y;
        As[ca + 2][ra] = pa.z;
        As[ca + 3][ra] = pa.w;
        *(float4*)&Bs[rb][cb] = pb;
        __syncthreads();

        if (kt + 1 < NT) {
            pa = *(const float4*)(g_attn + (size_t)(m0 + ra) * DM + (kt + 1) * BK + ca);
            pb = *(const float4*)(Wo + (size_t)((kt + 1) * BK + rb) * DM + cb);
        }

        #pragma unroll
        for (int kk = 0; kk < BK; kk++) {
            float a[8], b[8];
            *(float4*)(a)     = *(const float4*)&As[kk][ty * 8];
            *(float4*)(a + 4) = *(const float4*)&As[kk][ty * 8 + 4];
            *(float4*)(b)     = *(const float4*)&Bs[kk][tx * 8];
            *(float4*)(b + 4) = *(const float4*)&Bs[kk][tx * 8 + 4];
            #pragma unroll
            for (int i = 0; i < 8; i++)
                #pragma unroll
                for (int j = 0; j < 8; j++)
                    acc[i][j] = fmaf(a[i], b[j], acc[i][j]);
        }
        __syncthreads();
    }

    #pragma unroll
    for (int i = 0; i < 8; i++) {
        int m = m0 + ty * 8 + i;
        #pragma unroll
        for (int j = 0; j < 8; j += 4) {
            int c = tx * 8 + j;
            float4 r;
            r.x = fmaxf(acc[i][j + 0] + bo[c + 0], 0.f);
            r.y = fmaxf(acc[i][j + 1] + bo[c + 1], 0.f);
            r.z = fmaxf(acc[i][j + 2] + bo[c + 2], 0.f);
            r.w = fmaxf(acc[i][j + 3] + bo[c + 3], 0.f);
            *(float4*)&out[(size_t)m * DM + c] = r;
        }
    }
}

// ---------------------------------------------------------------------------
extern "C" void kernel_launch(void* const* d_in, const int* in_sizes, int n_in,
                              void* d_out, int out_size)
{
    const float* X   = (const float*)d_in[0];
    const float* STE = (const float*)d_in[1];
    const float* Wq  = (const float*)d_in[2];
    const float* bq  = (const float*)d_in[3];
    const float* Wk  = (const float*)d_in[4];
    const float* bk  = (const float*)d_in[5];
    const float* Wv  = (const float*)d_in[6];
    const float* bv  = (const float*)d_in[7];
    const float* Wo  = (const float*)d_in[8];
    const float* bo  = (const float*)d_in[9];
    float* out = (float*)d_out;

    qkv_kernel<<<dim3(NTOK / BM, 3), 256>>>(X, STE, Wq, Wk, Wv, bq, bk, bv);
    attn_kernel<<<BT * NH, 256>>>();
    out_kernel<<<NTOK / BM, 256>>>(Wo, bo, out);
}

// round 7
// speedup vs baseline: 1.2939x; 1.2939x over previous
#include <cuda_runtime.h>
#include <cuda_bf16.h>
#include <cstddef>

// ---------------------------------------------------------------------------
// SpatialAttention on GB300:
//  K0: wsplit  — pre-split/transpose weights to bf16 hi/lo packed words
//  K1: qkv     — bf16x3 tensor-core GEMM (mma.sync m16n8k16), relu+bias,
//                head-major scatter to f32 g_q/g_k/g_v
//  K2: attn    — fp32 flash-style softmax with packed fma.rn.f32x2 math,
//                writes output pre-split to bf16 hi/lo words (g_ah/g_al)
//  K3: out     — bf16x3 tensor-core GEMM (g_a @ Wo), relu+bias -> d_out (f32)
// ---------------------------------------------------------------------------

#define NTOK   49152      // B*T*N
#define BT     96         // B*T
#define SEQ    512        // N
#define DM     128        // D_MODEL
#define DH     16         // D_HEAD
#define NH     8          // heads
#define KDIM   384        // 3*DM
#define KW     (KDIM/2)   // 192 k-pair words per n column of W^T
#define KW3    (DM/2)     // 64 k-pair words per row for Wo^T / attn output
#define PITCH  9          // smem pitch in 32-bit words (18 bf16), conflict-light

typedef unsigned long long ull;

// f32 q/k/v for the attention kernel (head-major)
__device__ float    g_q[BT * NH * SEQ * DH];
__device__ float    g_k[BT * NH * SEQ * DH];
__device__ float    g_v[BT * NH * SEQ * DH];
// pre-split transposed weights: word = (bf16(k even) low | bf16(k odd) high)
__device__ unsigned g_WTh[3 * DM * KW];
__device__ unsigned g_WTl[3 * DM * KW];
__device__ unsigned g_WoTh[DM * KW3];
__device__ unsigned g_WoTl[DM * KW3];
// attention output, pre-split bf16 hi/lo, k-pair packed: [tok][64 words]
__device__ unsigned g_ah[(size_t)NTOK * KW3];
__device__ unsigned g_al[(size_t)NTOK * KW3];

// ---------------------------------------------------------------------------
// helpers
// ---------------------------------------------------------------------------
// pack two floats into bf16x2 word: low half = lo, high half = hi
__device__ __forceinline__ unsigned packbf(float lo, float hi) {
    unsigned r;
    asm("cvt.rn.satfinite.bf16x2.f32 %0, %1, %2;" : "=r"(r) : "f"(hi), "f"(lo));
    return r;
}

// split pair (x=k even, y=k odd) into hi word + residual lo word
__device__ __forceinline__ void split2(float x, float y, unsigned& h, unsigned& l) {
    h = packbf(x, y);
    float hx = __uint_as_float(h << 16);
    float hy = __uint_as_float(h & 0xffff0000u);
    l = packbf(x - hx, y - hy);
}

__device__ __forceinline__ void mma16816(float c[4], const unsigned a[4], const unsigned b[2]) {
    asm volatile(
        "mma.sync.aligned.m16n8k16.row.col.f32.bf16.bf16.f32 "
        "{%0,%1,%2,%3},{%4,%5,%6,%7},{%8,%9},{%0,%1,%2,%3};"
        : "+f"(c[0]), "+f"(c[1]), "+f"(c[2]), "+f"(c[3])
        : "r"(a[0]), "r"(a[1]), "r"(a[2]), "r"(a[3]), "r"(b[0]), "r"(b[1]));
}

// packed fp32x2 fma / add (Blackwell FFMA2 path — PTX-only)
__device__ __forceinline__ ull f2fma(ull a, ull b, ull c) {
    ull d;
    asm("fma.rn.f32x2 %0,%1,%2,%3;" : "=l"(d) : "l"(a), "l"(b), "l"(c));
    return d;
}
__device__ __forceinline__ float hsum2pair(ull a, ull b) {
    ull s;
    asm("add.rn.f32x2 %0,%1,%2;" : "=l"(s) : "l"(a), "l"(b));
    float x, y;
    asm("mov.b64 {%0,%1},%2;" : "=f"(x), "=f"(y) : "l"(s));
    return x + y;
}
__device__ __forceinline__ ull pk2(float x, float y) {
    ull r;
    asm("mov.b64 %0,{%1,%2};" : "=l"(r) : "f"(x), "f"(y));
    return r;
}
__device__ __forceinline__ float2 upk(ull v) {
    float2 f;
    asm("mov.b64 {%0,%1},%2;" : "=f"(f.x), "=f"(f.y) : "l"(v));
    return f;
}

// ---------------------------------------------------------------------------
// K0: weight pre-split. word idx layout [mat][n][kpair]  (k-major pairs per n)
// ---------------------------------------------------------------------------
__global__ void wsplit_kernel(const float* __restrict__ Wq, const float* __restrict__ Wk,
                              const float* __restrict__ Wv, const float* __restrict__ Wo)
{
    int idx = blockIdx.x * 256 + threadIdx.x;
    if (idx < 3 * DM * KW) {
        int mat = idx / (DM * KW);
        int rem = idx % (DM * KW);
        int n = rem / KW;
        int kp = rem % KW;
        const float* W = (mat == 0) ? Wq : (mat == 1) ? Wk : Wv;
        float x = W[(2 * kp) * DM + n];
        float y = W[(2 * kp + 1) * DM + n];
        unsigned h, l;
        split2(x, y, h, l);
        g_WTh[idx] = h;
        g_WTl[idx] = l;
    } else {
        int j = idx - 3 * DM * KW;
        if (j < DM * KW3) {
            int n = j / KW3;
            int kp = j % KW3;
            float x = Wo[(2 * kp) * DM + n];
            float y = Wo[(2 * kp + 1) * DM + n];
            unsigned h, l;
            split2(x, y, h, l);
            g_WoTh[j] = h;
            g_WoTl[j] = l;
        }
    }
}

// ---------------------------------------------------------------------------
// K1: qkv projection via bf16x3 mma. Block tile 128(M) x 128(N), 8 warps,
// warp tile 32x64 = 2(m16) x 8(n8) frags. K staged 16 per step (24 steps).
// ---------------------------------------------------------------------------
__device__ __forceinline__ float4 ldH(const float* __restrict__ X,
                                      const float* __restrict__ STE,
                                      int row, int col)
{
    return (col < DM) ? *(const float4*)(X + (size_t)row * DM + col)
                      : *(const float4*)(STE + (size_t)row * 256 + (col - DM));
}

__global__ void __launch_bounds__(256, 2)
qkv_kernel(const float* __restrict__ X, const float* __restrict__ STE,
           const float* __restrict__ bq, const float* __restrict__ bk,
           const float* __restrict__ bv)
{
    __shared__ __align__(16) unsigned SAh[128 * PITCH];
    __shared__ __align__(16) unsigned SAl[128 * PITCH];
    __shared__ __align__(16) unsigned SBh[128 * PITCH];
    __shared__ __align__(16) unsigned SBl[128 * PITCH];

    const int mblk = blockIdx.x;
    const int mat  = blockIdx.y;
    const float* bias = (mat == 0) ? bq : (mat == 1) ? bk : bv;
    float* out        = (mat == 0) ? g_q : (mat == 1) ? g_k : g_v;
    const unsigned* WTh = g_WTh + (size_t)mat * DM * KW;
    const unsigned* WTl = g_WTl + (size_t)mat * DM * KW;

    const int tid  = threadIdx.x;
    const int lane = tid & 31;
    const int warp = tid >> 5;
    const int wm = warp >> 1;       // 0..3
    const int wn = warp & 1;        // 0..1
    const int lq = lane >> 2;       // 0..7
    const int tq = lane & 3;        // 0..3
    const int m0 = mblk * 128;

    const int ar  = tid >> 1;       // A stage row 0..127
    const int ahf = tid & 1;        // A stage k-half
    const int bn  = tid & 127;      // B stage n
    const int bhf = tid >> 7;       // B stage k-half

    float acc[2][8][4];
    #pragma unroll
    for (int mt = 0; mt < 2; mt++)
        #pragma unroll
        for (int nt = 0; nt < 8; nt++)
            #pragma unroll
            for (int i = 0; i < 4; i++) acc[mt][nt][i] = 0.f;

    const int NT = KDIM / 16;       // 24

    // prefetch kstep 0
    float4 pa0 = ldH(X, STE, m0 + ar, 0 * 16 + ahf * 8);
    float4 pa1 = ldH(X, STE, m0 + ar, 0 * 16 + ahf * 8 + 4);
    uint4 pbh = *(const uint4*)(WTh + (size_t)bn * KW + 0 * 8 + bhf * 4);
    uint4 pbl = *(const uint4*)(WTl + (size_t)bn * KW + 0 * 8 + bhf * 4);

    for (int kt = 0; kt < NT; ++kt) {
        __syncthreads();
        // stage A (split f32 -> bf16 hi/lo pair words) and B (copy)
        {
            int base = ar * PITCH + ahf * 4;
            unsigned h, l;
            split2(pa0.x, pa0.y, h, l); SAh[base + 0] = h; SAl[base + 0] = l;
            split2(pa0.z, pa0.w, h, l); SAh[base + 1] = h; SAl[base + 1] = l;
            split2(pa1.x, pa1.y, h, l); SAh[base + 2] = h; SAl[base + 2] = l;
            split2(pa1.z, pa1.w, h, l); SAh[base + 3] = h; SAl[base + 3] = l;
            int bb = bn * PITCH + bhf * 4;
            SBh[bb + 0] = pbh.x; SBh[bb + 1] = pbh.y; SBh[bb + 2] = pbh.z; SBh[bb + 3] = pbh.w;
            SBl[bb + 0] = pbl.x; SBl[bb + 1] = pbl.y; SBl[bb + 2] = pbl.z; SBl[bb + 3] = pbl.w;
        }
        __syncthreads();

        if (kt + 1 < NT) {
            pa0 = ldH(X, STE, m0 + ar, (kt + 1) * 16 + ahf * 8);
            pa1 = ldH(X, STE, m0 + ar, (kt + 1) * 16 + ahf * 8 + 4);
            pbh = *(const uint4*)(WTh + (size_t)bn * KW + (kt + 1) * 8 + bhf * 4);
            pbl = *(const uint4*)(WTl + (size_t)bn * KW + (kt + 1) * 8 + bhf * 4);
        }

        // A fragments
        unsigned ah[2][4], al[2][4];
        #pragma unroll
        for (int mt = 0; mt < 2; mt++) {
            int rb = wm * 32 + mt * 16 + lq;
            ah[mt][0] = SAh[rb * PITCH + tq];
            ah[mt][1] = SAh[(rb + 8) * PITCH + tq];
            ah[mt][2] = SAh[rb * PITCH + 4 + tq];
            ah[mt][3] = SAh[(rb + 8) * PITCH + 4 + tq];
            al[mt][0] = SAl[rb * PITCH + tq];
            al[mt][1] = SAl[(rb + 8) * PITCH + tq];
            al[mt][2] = SAl[rb * PITCH + 4 + tq];
            al[mt][3] = SAl[(rb + 8) * PITCH + 4 + tq];
        }

        #pragma unroll
        for (int nt = 0; nt < 8; nt++) {
            int nb = wn * 64 + nt * 8 + lq;
            unsigned bh[2], bl[2];
            bh[0] = SBh[nb * PITCH + tq];
            bh[1] = SBh[nb * PITCH + 4 + tq];
            bl[0] = SBl[nb * PITCH + tq];
            bl[1] = SBl[nb * PITCH + 4 + tq];
            #pragma unroll
            for (int mt = 0; mt < 2; mt++) {
                mma16816(acc[mt][nt], ah[mt], bh);   // hi*hi
                mma16816(acc[mt][nt], al[mt], bh);   // lo*hi
                mma16816(acc[mt][nt], ah[mt], bl);   // hi*lo
            }
        }
    }

    // epilogue: bias + relu, head-major scatter to f32 q/k/v
    #pragma unroll
    for (int mt = 0; mt < 2; mt++) {
        int r0 = m0 + wm * 32 + mt * 16 + lq;
        int btk = r0 >> 9;
        int n0  = r0 & 511;
        #pragma unroll
        for (int nt = 0; nt < 8; nt++) {
            int c = wn * 64 + nt * 8 + tq * 2;
            float b0 = bias[c], b1 = bias[c + 1];
            int h = c >> 4, d = c & 15;
            float2 v0, v1;
            v0.x = fmaxf(acc[mt][nt][0] + b0, 0.f);
            v0.y = fmaxf(acc[mt][nt][1] + b1, 0.f);
            v1.x = fmaxf(acc[mt][nt][2] + b0, 0.f);
            v1.y = fmaxf(acc[mt][nt][3] + b1, 0.f);
            *(float2*)&out[((size_t)(btk * NH + h) * SEQ + n0) * DH + d]       = v0;
            *(float2*)&out[((size_t)(btk * NH + h) * SEQ + (n0 + 8)) * DH + d] = v1;
        }
    }
}

// ---------------------------------------------------------------------------
// K2: attention per (bt, head), fp32 with packed f32x2 FMA.
// Softmax without running max: s = q.k/4 bounded, exp(s-8) safe in fp32;
// the -8 shift cancels exactly in o/L. Output written pre-split bf16 hi/lo.
// ---------------------------------------------------------------------------
#define CHUNK 256

__global__ void __launch_bounds__(256, 2)
attn_kernel()
{
    __shared__ __align__(16) float sk[CHUNK * DH];
    __shared__ __align__(16) float sv[CHUNK * DH];

    const int bth = blockIdx.x;              // bt*8 + h
    const size_t base = (size_t)bth * (SEQ * DH);
    const int tid = threadIdx.x;

    ull q0p[8], q1p[8];
    {
        const ulonglong2* qp0 = (const ulonglong2*)(g_q + base + (size_t)tid * DH);
        const ulonglong2* qp1 = (const ulonglong2*)(g_q + base + (size_t)(tid + 256) * DH);
        #pragma unroll
        for (int j = 0; j < 4; j++) {
            ulonglong2 t0 = qp0[j], t1 = qp1[j];
            q0p[2 * j] = t0.x; q0p[2 * j + 1] = t0.y;
            q1p[2 * j] = t1.x; q1p[2 * j + 1] = t1.y;
        }
    }

    ull o0p[8], o1p[8];
    #pragma unroll
    for (int j = 0; j < 8; j++) { o0p[j] = 0ull; o1p[j] = 0ull; }
    float L0 = 0.f, L1 = 0.f;

    for (int ch = 0; ch < SEQ / CHUNK; ++ch) {
        const float4* kp = (const float4*)(g_k + base + (size_t)ch * CHUNK * DH);
        const float4* vp = (const float4*)(g_v + base + (size_t)ch * CHUNK * DH);
        #pragma unroll
        for (int j = 0; j < 4; j++) {
            ((float4*)sk)[tid + j * 256] = kp[tid + j * 256];
            ((float4*)sv)[tid + j * 256] = vp[tid + j * 256];
        }
        __syncthreads();

        for (int m = 0; m < CHUNK; m++) {
            ull kr[8];
            {
                const ulonglong2* kp2 = (const ulonglong2*)sk + m * 4;
                #pragma unroll
                for (int j = 0; j < 4; j++) {
                    ulonglong2 t = kp2[j];
                    kr[2 * j] = t.x; kr[2 * j + 1] = t.y;
                }
            }
            ull s0a = 0ull, s0b = 0ull, s1a = 0ull, s1b = 0ull;
            #pragma unroll
            for (int j = 0; j < 4; j++) {
                s0a = f2fma(q0p[2 * j],     kr[2 * j],     s0a);
                s0b = f2fma(q0p[2 * j + 1], kr[2 * j + 1], s0b);
                s1a = f2fma(q1p[2 * j],     kr[2 * j],     s1a);
                s1b = f2fma(q1p[2 * j + 1], kr[2 * j + 1], s1b);
            }
            float s0 = hsum2pair(s0a, s0b);
            float s1 = hsum2pair(s1a, s1b);
            float p0 = __expf(fmaf(s0, 0.25f, -8.0f));
            float p1 = __expf(fmaf(s1, 0.25f, -8.0f));
            L0 += p0;
            L1 += p1;
            ull pp0 = pk2(p0, p0);
            ull pp1 = pk2(p1, p1);

            ull vr[8];
            {
                const ulonglong2* vp2 = (const ulonglong2*)sv + m * 4;
                #pragma unroll
                for (int j = 0; j < 4; j++) {
                    ulonglong2 t = vp2[j];
                    vr[2 * j] = t.x; vr[2 * j + 1] = t.y;
                }
            }
            #pragma unroll
            for (int j = 0; j < 8; j++) {
                o0p[j] = f2fma(pp0, vr[j], o0p[j]);
                o1p[j] = f2fma(pp1, vr[j], o1p[j]);
            }
        }
        __syncthreads();
    }

    const float inv0 = 1.f / L0;
    const float inv1 = 1.f / L1;
    const int btk = bth >> 3;
    const int h   = bth & 7;

    // unpack, normalize, split to bf16 hi/lo pair words, store 2x uint4 each
    unsigned hw0[8], lw0[8], hw1[8], lw1[8];
    #pragma unroll
    for (int j = 0; j < 8; j++) {
        float2 f0 = upk(o0p[j]);
        float2 f1 = upk(o1p[j]);
        split2(f0.x * inv0, f0.y * inv0, hw0[j], lw0[j]);
        split2(f1.x * inv1, f1.y * inv1, hw1[j], lw1[j]);
    }
    unsigned* d0h = g_ah + (size_t)(btk * SEQ + tid) * KW3 + h * 8;
    unsigned* d0l = g_al + (size_t)(btk * SEQ + tid) * KW3 + h * 8;
    unsigned* d1h = g_ah + (size_t)(btk * SEQ + tid + 256) * KW3 + h * 8;
    unsigned* d1l = g_al + (size_t)(btk * SEQ + tid + 256) * KW3 + h * 8;
    *(uint4*)(d0h)     = make_uint4(hw0[0], hw0[1], hw0[2], hw0[3]);
    *(uint4*)(d0h + 4) = make_uint4(hw0[4], hw0[5], hw0[6], hw0[7]);
    *(uint4*)(d0l)     = make_uint4(lw0[0], lw0[1], lw0[2], lw0[3]);
    *(uint4*)(d0l + 4) = make_uint4(lw0[4], lw0[5], lw0[6], lw0[7]);
    *(uint4*)(d1h)     = make_uint4(hw1[0], hw1[1], hw1[2], hw1[3]);
    *(uint4*)(d1h + 4) = make_uint4(hw1[4], hw1[5], hw1[6], hw1[7]);
    *(uint4*)(d1l)     = make_uint4(lw1[0], lw1[1], lw1[2], lw1[3]);
    *(uint4*)(d1l + 4) = make_uint4(lw1[4], lw1[5], lw1[6], lw1[7]);
}

// ---------------------------------------------------------------------------
// K3: output projection via bf16x3 mma. A pre-split by K2, B pre-split by K0.
// M=49152, N=128, K=128 (8 ksteps). Same tile structure as K1.
// ---------------------------------------------------------------------------
__global__ void __launch_bounds__(256, 2)
out_kernel(const float* __restrict__ bo, float* __restrict__ out)
{
    __shared__ __align__(16) unsigned SAh[128 * PITCH];
    __shared__ __align__(16) unsigned SAl[128 * PITCH];
    __shared__ __align__(16) unsigned SBh[128 * PITCH];
    __shared__ __align__(16) unsigned SBl[128 * PITCH];

    const int mblk = blockIdx.x;
    const int tid  = threadIdx.x;
    const int lane = tid & 31;
    const int warp = tid >> 5;
    const int wm = warp >> 1;
    const int wn = warp & 1;
    const int lq = lane >> 2;
    const int tq = lane & 3;
    const int m0 = mblk * 128;

    const int ar  = tid >> 1;
    const int ahf = tid & 1;
    const int bn  = tid & 127;
    const int bhf = tid >> 7;

    float acc[2][8][4];
    #pragma unroll
    for (int mt = 0; mt < 2; mt++)
        #pragma unroll
        for (int nt = 0; nt < 8; nt++)
            #pragma unroll
            for (int i = 0; i < 4; i++) acc[mt][nt][i] = 0.f;

    const int NT = DM / 16;   // 8

    uint4 pah = *(const uint4*)(g_ah + (size_t)(m0 + ar) * KW3 + 0 * 8 + ahf * 4);
    uint4 pal = *(const uint4*)(g_al + (size_t)(m0 + ar) * KW3 + 0 * 8 + ahf * 4);
    uint4 pbh = *(const uint4*)(g_WoTh + (size_t)bn * KW3 + 0 * 8 + bhf * 4);
    uint4 pbl = *(const uint4*)(g_WoTl + (size_t)bn * KW3 + 0 * 8 + bhf * 4);

    for (int kt = 0; kt < NT; ++kt) {
        __syncthreads();
        {
            int base = ar * PITCH + ahf * 4;
            SAh[base + 0] = pah.x; SAh[base + 1] = pah.y; SAh[base + 2] = pah.z; SAh[base + 3] = pah.w;
            SAl[base + 0] = pal.x; SAl[base + 1] = pal.y; SAl[base + 2] = pal.z; SAl[base + 3] = pal.w;
            int bb = bn * PITCH + bhf * 4;
            SBh[bb + 0] = pbh.x; SBh[bb + 1] = pbh.y; SBh[bb + 2] = pbh.z; SBh[bb + 3] = pbh.w;
            SBl[bb + 0] = pbl.x; SBl[bb + 1] = pbl.y; SBl[bb + 2] = pbl.z; SBl[bb + 3] = pbl.w;
        }
        __syncthreads();

        if (kt + 1 < NT) {
            pah = *(const uint4*)(g_ah + (size_t)(m0 + ar) * KW3 + (kt + 1) * 8 + ahf * 4);
            pal = *(const uint4*)(g_al + (size_t)(m0 + ar) * KW3 + (kt + 1) * 8 + ahf * 4);
            pbh = *(const uint4*)(g_WoTh + (size_t)bn * KW3 + (kt + 1) * 8 + bhf * 4);
            pbl = *(const uint4*)(g_WoTl + (size_t)bn * KW3 + (kt + 1) * 8 + bhf * 4);
        }

        unsigned ah[2][4], al[2][4];
        #pragma unroll
        for (int mt = 0; mt < 2; mt++) {
            int rb = wm * 32 + mt * 16 + lq;
            ah[mt][0] = SAh[rb * PITCH + tq];
            ah[mt][1] = SAh[(rb + 8) * PITCH + tq];
            ah[mt][2] = SAh[rb * PITCH + 4 + tq];
            ah[mt][3] = SAh[(rb + 8) * PITCH + 4 + tq];
            al[mt][0] = SAl[rb * PITCH + tq];
            al[mt][1] = SAl[(rb + 8) * PITCH + tq];
            al[mt][2] = SAl[rb * PITCH + 4 + tq];
            al[mt][3] = SAl[(rb + 8) * PITCH + 4 + tq];
        }

        #pragma unroll
        for (int nt = 0; nt < 8; nt++) {
            int nb = wn * 64 + nt * 8 + lq;
            unsigned bh[2], bl[2];
            bh[0] = SBh[nb * PITCH + tq];
            bh[1] = SBh[nb * PITCH + 4 + tq];
            bl[0] = SBl[nb * PITCH + tq];
            bl[1] = SBl[nb * PITCH + 4 + tq];
            #pragma unroll
            for (int mt = 0; mt < 2; mt++) {
                mma16816(acc[mt][nt], ah[mt], bh);
                mma16816(acc[mt][nt], al[mt], bh);
                mma16816(acc[mt][nt], ah[mt], bl);
            }
        }
    }

    #pragma unroll
    for (int mt = 0; mt < 2; mt++) {
        int r0 = m0 + wm * 32 + mt * 16 + lq;
        #pragma unroll
        for (int nt = 0; nt < 8; nt++) {
            int c = wn * 64 + nt * 8 + tq * 2;
            float b0 = bo[c], b1 = bo[c + 1];
            float2 v0, v1;
            v0.x = fmaxf(acc[mt][nt][0] + b0, 0.f);
            v0.y = fmaxf(acc[mt][nt][1] + b1, 0.f);
            v1.x = fmaxf(acc[mt][nt][2] + b0, 0.f);
            v1.y = fmaxf(acc[mt][nt][3] + b1, 0.f);
            *(float2*)&out[(size_t)r0 * DM + c]       = v0;
            *(float2*)&out[(size_t)(r0 + 8) * DM + c] = v1;
        }
    }
}

// ---------------------------------------------------------------------------
extern "C" void kernel_launch(void* const* d_in, const int* in_sizes, int n_in,
                              void* d_out, int out_size)
{
    const float* X   = (const float*)d_in[0];
    const float* STE = (const float*)d_in[1];
    const float* Wq  = (const float*)d_in[2];
    const float* bq  = (const float*)d_in[3];
    const float* Wk  = (const float*)d_in[4];
    const float* bk  = (const float*)d_in[5];
    const float* Wv  = (const float*)d_in[6];
    const float* bv  = (const float*)d_in[7];
    const float* Wo  = (const float*)d_in[8];
    const float* bo  = (const float*)d_in[9];
    float* out = (float*)d_out;

    wsplit_kernel<<<(3 * DM * KW + DM * KW3 + 255) / 256, 256>>>(Wq, Wk, Wv, Wo);
    qkv_kernel<<<dim3(NTOK / 128, 3), 256>>>(X, STE, bq, bk, bv);
    attn_kernel<<<BT * NH, 256>>>();
    out_kernel<<<NTOK / 128, 256>>>(bo, out);
}

// round 8
// speedup vs baseline: 2.1898x; 1.6923x over previous
#include <cuda_runtime.h>
#include <cuda_bf16.h>
#include <cstddef>

// ---------------------------------------------------------------------------
// SpatialAttention on GB300 (sm_103a):
//  K0: wsplit  — pre-split/transpose weights to bf16 hi/lo packed words
//  K1: qkv     — bf16x3 tensor-core GEMM, relu+bias, writes q/k pre-split
//                bf16 hi/lo + v bf16 (head-major, d-pair packed words)
//  K2: attn    — tensor-core flash attention: S=QK^T bf16x3, exp (no-max
//                softmax), P@V single bf16; output pre-split bf16 -> g_ah/g_al
//  K3: out     — bf16x3 tensor-core GEMM (g_a @ Wo), relu+bias -> f32 out
// ---------------------------------------------------------------------------

#define NTOK   49152      // B*T*N
#define BT     96         // B*T
#define SEQ    512        // N
#define DM     128        // D_MODEL
#define DH     16         // D_HEAD
#define NH     8          // heads
#define KDIM   384        // 3*DM
#define KW     (KDIM/2)   // 192 k-pair words per n column of W^T
#define KW3    (DM/2)     // 64 k-pair words per row
#define PITCH  9          // GEMM smem pitch in words

// pre-split transposed weights: word = (bf16(k even) low | bf16(k odd) high)
__device__ unsigned g_WTh[3 * DM * KW];
__device__ unsigned g_WTl[3 * DM * KW];
__device__ unsigned g_WoTh[DM * KW3];
__device__ unsigned g_WoTl[DM * KW3];
// q/k/v head-major, d-pair packed bf16 words: [(bt*8+h)*512 + n][8]
__device__ unsigned g_qh[BT * NH * SEQ * 8];
__device__ unsigned g_ql[BT * NH * SEQ * 8];
__device__ unsigned g_kh[BT * NH * SEQ * 8];
__device__ unsigned g_kl[BT * NH * SEQ * 8];
__device__ unsigned g_vh[BT * NH * SEQ * 8];
// attention output, pre-split bf16 hi/lo, k-pair packed: [tok][64 words]
__device__ unsigned g_ah[(size_t)NTOK * KW3];
__device__ unsigned g_al[(size_t)NTOK * KW3];

// ---------------------------------------------------------------------------
// helpers
// ---------------------------------------------------------------------------
__device__ __forceinline__ unsigned packbf(float lo, float hi) {
    unsigned r;
    asm("cvt.rn.satfinite.bf16x2.f32 %0, %1, %2;" : "=r"(r) : "f"(hi), "f"(lo));
    return r;
}

__device__ __forceinline__ void split2(float x, float y, unsigned& h, unsigned& l) {
    h = packbf(x, y);
    float hx = __uint_as_float(h << 16);
    float hy = __uint_as_float(h & 0xffff0000u);
    l = packbf(x - hx, y - hy);
}

__device__ __forceinline__ unsigned prmt(unsigned a, unsigned b, unsigned sel) {
    unsigned r;
    asm("prmt.b32 %0,%1,%2,%3;" : "=r"(r) : "r"(a), "r"(b), "r"(sel));
    return r;
}

__device__ __forceinline__ void mma16816(float c[4], const unsigned a[4], const unsigned b[2]) {
    asm volatile(
        "mma.sync.aligned.m16n8k16.row.col.f32.bf16.bf16.f32 "
        "{%0,%1,%2,%3},{%4,%5,%6,%7},{%8,%9},{%0,%1,%2,%3};"
        : "+f"(c[0]), "+f"(c[1]), "+f"(c[2]), "+f"(c[3])
        : "r"(a[0]), "r"(a[1]), "r"(a[2]), "r"(a[3]), "r"(b[0]), "r"(b[1]));
}

// ---------------------------------------------------------------------------
// K0: weight pre-split. word idx layout [mat][n][kpair]
// ---------------------------------------------------------------------------
__global__ void wsplit_kernel(const float* __restrict__ Wq, const float* __restrict__ Wk,
                              const float* __restrict__ Wv, const float* __restrict__ Wo)
{
    int idx = blockIdx.x * 256 + threadIdx.x;
    if (idx < 3 * DM * KW) {
        int mat = idx / (DM * KW);
        int rem = idx % (DM * KW);
        int n = rem / KW;
        int kp = rem % KW;
        const float* W = (mat == 0) ? Wq : (mat == 1) ? Wk : Wv;
        unsigned h, l;
        split2(W[(2 * kp) * DM + n], W[(2 * kp + 1) * DM + n], h, l);
        g_WTh[idx] = h;
        g_WTl[idx] = l;
    } else {
        int j = idx - 3 * DM * KW;
        if (j < DM * KW3) {
            int n = j / KW3;
            int kp = j % KW3;
            unsigned h, l;
            split2(Wo[(2 * kp) * DM + n], Wo[(2 * kp + 1) * DM + n], h, l);
            g_WoTh[j] = h;
            g_WoTl[j] = l;
        }
    }
}

// ---------------------------------------------------------------------------
// K1: qkv projection, bf16x3 mma, double-buffered smem.
// Block tile 128x128, 8 warps (warp 32x64), K staged 16/step (24 steps).
// ---------------------------------------------------------------------------
__device__ __forceinline__ float4 ldH(const float* __restrict__ X,
                                      const float* __restrict__ STE,
                                      int row, int col)
{
    return (col < DM) ? *(const float4*)(X + (size_t)row * DM + col)
                      : *(const float4*)(STE + (size_t)row * 256 + (col - DM));
}

__global__ void __launch_bounds__(256, 2)
qkv_kernel(const float* __restrict__ X, const float* __restrict__ STE,
           const float* __restrict__ bq, const float* __restrict__ bk,
           const float* __restrict__ bv)
{
    __shared__ __align__(16) unsigned SAh[2][128 * PITCH];
    __shared__ __align__(16) unsigned SAl[2][128 * PITCH];
    __shared__ __align__(16) unsigned SBh[2][128 * PITCH];
    __shared__ __align__(16) unsigned SBl[2][128 * PITCH];

    const int mblk = blockIdx.x;
    const int mat  = blockIdx.y;
    const float* bias = (mat == 0) ? bq : (mat == 1) ? bk : bv;
    const unsigned* WTh = g_WTh + (size_t)mat * DM * KW;
    const unsigned* WTl = g_WTl + (size_t)mat * DM * KW;
    unsigned* outh = (mat == 0) ? g_qh : (mat == 1) ? g_kh : g_vh;
    unsigned* outl = (mat == 0) ? g_ql : g_kl;   // only used when mat<2

    const int tid  = threadIdx.x;
    const int lane = tid & 31;
    const int warp = tid >> 5;
    const int wm = warp >> 1;
    const int wn = warp & 1;
    const int lq = lane >> 2;
    const int tq = lane & 3;
    const int m0 = mblk * 128;

    const int ar  = tid >> 1;
    const int ahf = tid & 1;
    const int bn  = tid & 127;
    const int bhf = tid >> 7;

    float acc[2][8][4];
    #pragma unroll
    for (int mt = 0; mt < 2; mt++)
        #pragma unroll
        for (int nt = 0; nt < 8; nt++)
            #pragma unroll
            for (int i = 0; i < 4; i++) acc[mt][nt][i] = 0.f;

    const int NT = KDIM / 16;   // 24

    float4 pa0 = ldH(X, STE, m0 + ar, ahf * 8);
    float4 pa1 = ldH(X, STE, m0 + ar, ahf * 8 + 4);
    uint4 pbh = *(const uint4*)(WTh + (size_t)bn * KW + bhf * 4);
    uint4 pbl = *(const uint4*)(WTl + (size_t)bn * KW + bhf * 4);

    // stage buffer 0
    {
        int base = ar * PITCH + ahf * 4;
        unsigned h, l;
        split2(pa0.x, pa0.y, h, l); SAh[0][base + 0] = h; SAl[0][base + 0] = l;
        split2(pa0.z, pa0.w, h, l); SAh[0][base + 1] = h; SAl[0][base + 1] = l;
        split2(pa1.x, pa1.y, h, l); SAh[0][base + 2] = h; SAl[0][base + 2] = l;
        split2(pa1.z, pa1.w, h, l); SAh[0][base + 3] = h; SAl[0][base + 3] = l;
        int bb = bn * PITCH + bhf * 4;
        SBh[0][bb + 0] = pbh.x; SBh[0][bb + 1] = pbh.y; SBh[0][bb + 2] = pbh.z; SBh[0][bb + 3] = pbh.w;
        SBl[0][bb + 0] = pbl.x; SBl[0][bb + 1] = pbl.y; SBl[0][bb + 2] = pbl.z; SBl[0][bb + 3] = pbl.w;
    }
    __syncthreads();

    for (int kt = 0; kt < NT; ++kt) {
        const int cur = kt & 1, nxt = cur ^ 1;
        if (kt + 1 < NT) {
            pa0 = ldH(X, STE, m0 + ar, (kt + 1) * 16 + ahf * 8);
            pa1 = ldH(X, STE, m0 + ar, (kt + 1) * 16 + ahf * 8 + 4);
            pbh = *(const uint4*)(WTh + (size_t)bn * KW + (kt + 1) * 8 + bhf * 4);
            pbl = *(const uint4*)(WTl + (size_t)bn * KW + (kt + 1) * 8 + bhf * 4);
        }

        unsigned ah[2][4], al[2][4];
        #pragma unroll
        for (int mt = 0; mt < 2; mt++) {
            int rb = wm * 32 + mt * 16 + lq;
            ah[mt][0] = SAh[cur][rb * PITCH + tq];
            ah[mt][1] = SAh[cur][(rb + 8) * PITCH + tq];
            ah[mt][2] = SAh[cur][rb * PITCH + 4 + tq];
            ah[mt][3] = SAh[cur][(rb + 8) * PITCH + 4 + tq];
            al[mt][0] = SAl[cur][rb * PITCH + tq];
            al[mt][1] = SAl[cur][(rb + 8) * PITCH + tq];
            al[mt][2] = SAl[cur][rb * PITCH + 4 + tq];
            al[mt][3] = SAl[cur][(rb + 8) * PITCH + 4 + tq];
        }

        #pragma unroll
        for (int nt = 0; nt < 8; nt++) {
            int nb = wn * 64 + nt * 8 + lq;
            unsigned bh[2], bl[2];
            bh[0] = SBh[cur][nb * PITCH + tq];
            bh[1] = SBh[cur][nb * PITCH + 4 + tq];
            bl[0] = SBl[cur][nb * PITCH + tq];
            bl[1] = SBl[cur][nb * PITCH + 4 + tq];
            #pragma unroll
            for (int mt = 0; mt < 2; mt++) {
                mma16816(acc[mt][nt], ah[mt], bh);
                mma16816(acc[mt][nt], al[mt], bh);
                mma16816(acc[mt][nt], ah[mt], bl);
            }
        }

        if (kt + 1 < NT) {
            int base = ar * PITCH + ahf * 4;
            unsigned h, l;
            split2(pa0.x, pa0.y, h, l); SAh[nxt][base + 0] = h; SAl[nxt][base + 0] = l;
            split2(pa0.z, pa0.w, h, l); SAh[nxt][base + 1] = h; SAl[nxt][base + 1] = l;
            split2(pa1.x, pa1.y, h, l); SAh[nxt][base + 2] = h; SAl[nxt][base + 2] = l;
            split2(pa1.z, pa1.w, h, l); SAh[nxt][base + 3] = h; SAl[nxt][base + 3] = l;
            int bb = bn * PITCH + bhf * 4;
            SBh[nxt][bb + 0] = pbh.x; SBh[nxt][bb + 1] = pbh.y; SBh[nxt][bb + 2] = pbh.z; SBh[nxt][bb + 3] = pbh.w;
            SBl[nxt][bb + 0] = pbl.x; SBl[nxt][bb + 1] = pbl.y; SBl[nxt][bb + 2] = pbl.z; SBl[nxt][bb + 3] = pbl.w;
        }
        __syncthreads();
    }

    // epilogue: relu(acc+bias), split bf16 hi/lo, head-major d-pair words
    #pragma unroll
    for (int mt = 0; mt < 2; mt++) {
        int r0 = m0 + wm * 32 + mt * 16 + lq;
        int btk = r0 >> 9;
        int n0  = r0 & 511;
        #pragma unroll
        for (int nt = 0; nt < 8; nt++) {
            int c = wn * 64 + nt * 8 + tq * 2;
            int h = c >> 4, dp = (c & 15) >> 1;
            float b0 = bias[c], b1 = bias[c + 1];
            size_t w0 = ((size_t)(btk * NH + h) * SEQ + n0) * 8 + dp;
            size_t w1 = ((size_t)(btk * NH + h) * SEQ + n0 + 8) * 8 + dp;
            unsigned hw, lw;
            split2(fmaxf(acc[mt][nt][0] + b0, 0.f), fmaxf(acc[mt][nt][1] + b1, 0.f), hw, lw);
            outh[w0] = hw;
            if (mat < 2) outl[w0] = lw;
            split2(fmaxf(acc[mt][nt][2] + b0, 0.f), fmaxf(acc[mt][nt][3] + b1, 0.f), hw, lw);
            outh[w1] = hw;
            if (mat < 2) outl[w1] = lw;
        }
    }
}

// ---------------------------------------------------------------------------
// K2: tensor-core attention. Block = (bt, head): 8 warps, warp = 64 q rows.
// S = QK^T bf16x3 (m16n8k16), p = exp(s/4 - 8) (scores bounded, no max pass;
// the -8 shift cancels in o/L), O += P@V in single bf16.
// K/V staged in smem; V transpose-packed (key-pair per d) with XOR swizzle.
// ---------------------------------------------------------------------------
__device__ __forceinline__ int sVidx(int d, int kp) {
    return d * 256 + (kp ^ ((d & 7) << 2));
}

__global__ void __launch_bounds__(256, 2)
attn_kernel()
{
    __shared__ unsigned sKh[512 * 8];   // 16KB
    __shared__ unsigned sKl[512 * 8];   // 16KB
    __shared__ unsigned sV[16 * 256];   // 16KB, swizzled [d][kp]

    const int bth = blockIdx.x;
    const int tid = threadIdx.x;
    const int lane = tid & 31;
    const int warp = tid >> 5;
    const int lq = lane >> 2;
    const int tq = lane & 3;
    const size_t kvbase = (size_t)bth * (SEQ * 8);

    // stage K hi/lo (straight copy)
    {
        const uint4* gh = (const uint4*)(g_kh + kvbase);
        const uint4* gl = (const uint4*)(g_kl + kvbase);
        uint4* sh = (uint4*)sKh;
        uint4* sl = (uint4*)sKl;
        #pragma unroll
        for (int j = 0; j < 4; j++) {
            sh[tid + j * 256] = gh[tid + j * 256];
            sl[tid + j * 256] = gl[tid + j * 256];
        }
    }
    // stage V transpose-packed: out word (d, kp) = (V[2kp][d], V[2kp+1][d])
    {
        const uint4* gv = (const uint4*)(g_vh + kvbase);
        int kp = tid;                       // 0..255
        uint4 a0 = gv[kp * 4 + 0];          // row 2kp,   dpairs 0..3
        uint4 a1 = gv[kp * 4 + 1];          // row 2kp,   dpairs 4..7
        uint4 b0 = gv[kp * 4 + 2];          // row 2kp+1, dpairs 0..3
        uint4 b1 = gv[kp * 4 + 3];          // row 2kp+1, dpairs 4..7
        unsigned ia[8] = {a0.x, a0.y, a0.z, a0.w, a1.x, a1.y, a1.z, a1.w};
        unsigned ib[8] = {b0.x, b0.y, b0.z, b0.w, b1.x, b1.y, b1.z, b1.w};
        #pragma unroll
        for (int dp = 0; dp < 8; dp++) {
            sV[sVidx(2 * dp,     kp)] = prmt(ia[dp], ib[dp], 0x5410);
            sV[sVidx(2 * dp + 1, kp)] = prmt(ia[dp], ib[dp], 0x7632);
        }
    }
    __syncthreads();

    // persistent Q fragments (hi + lo), warp rows 64*warp .. +63
    const unsigned* qh = g_qh + kvbase;
    const unsigned* ql = g_ql + kvbase;
    unsigned qah[4][4], qal[4][4];
    #pragma unroll
    for (int mt = 0; mt < 4; mt++) {
        int r = warp * 64 + mt * 16 + lq;
        qah[mt][0] = qh[(size_t)r * 8 + tq];
        qah[mt][1] = qh[(size_t)(r + 8) * 8 + tq];
        qah[mt][2] = qh[(size_t)r * 8 + tq + 4];
        qah[mt][3] = qh[(size_t)(r + 8) * 8 + tq + 4];
        qal[mt][0] = ql[(size_t)r * 8 + tq];
        qal[mt][1] = ql[(size_t)(r + 8) * 8 + tq];
        qal[mt][2] = ql[(size_t)r * 8 + tq + 4];
        qal[mt][3] = ql[(size_t)(r + 8) * 8 + tq + 4];
    }

    float oacc[4][2][4];
    float Lp[4][2];
    #pragma unroll
    for (int mt = 0; mt < 4; mt++) {
        Lp[mt][0] = 0.f; Lp[mt][1] = 0.f;
        #pragma unroll
        for (int nc = 0; nc < 2; nc++)
            #pragma unroll
            for (int i = 0; i < 4; i++) oacc[mt][nc][i] = 0.f;
    }

    for (int c = 0; c < 32; c++) {        // 16 keys per chunk
        unsigned bh[2][2], bl[2][2], bv[2][2];
        #pragma unroll
        for (int nc = 0; nc < 2; nc++) {
            int kb = c * 16 + nc * 8 + lq;           // key index for B frag
            bh[nc][0] = sKh[kb * 8 + tq];
            bh[nc][1] = sKh[kb * 8 + tq + 4];
            bl[nc][0] = sKl[kb * 8 + tq];
            bl[nc][1] = sKl[kb * 8 + tq + 4];
            bv[nc][0] = sV[sVidx(nc * 8 + lq, c * 8 + tq)];
            bv[nc][1] = sV[sVidx(nc * 8 + lq, c * 8 + tq + 4)];
        }
        #pragma unroll
        for (int mt = 0; mt < 4; mt++) {
            float s[2][4];
            #pragma unroll
            for (int nc = 0; nc < 2; nc++) {
                #pragma unroll
                for (int i = 0; i < 4; i++) s[nc][i] = 0.f;
                mma16816(s[nc], qah[mt], bh[nc]);   // hi*hi
                mma16816(s[nc], qal[mt], bh[nc]);   // lo*hi
                mma16816(s[nc], qah[mt], bl[nc]);   // hi*lo
                #pragma unroll
                for (int i = 0; i < 4; i++)
                    s[nc][i] = __expf(fmaf(s[nc][i], 0.25f, -8.0f));
            }
            Lp[mt][0] += s[0][0] + s[0][1] + s[1][0] + s[1][1];
            Lp[mt][1] += s[0][2] + s[0][3] + s[1][2] + s[1][3];
            // accum layout == A layout: pack P as A frags for PV mma
            unsigned pA[4] = { packbf(s[0][0], s[0][1]), packbf(s[0][2], s[0][3]),
                               packbf(s[1][0], s[1][1]), packbf(s[1][2], s[1][3]) };
            mma16816(oacc[mt][0], pA, bv[0]);       // d 0..7
            mma16816(oacc[mt][1], pA, bv[1]);       // d 8..15
        }
    }

    // row-sum reduce across the 4 lanes sharing a row, then invert
    #pragma unroll
    for (int mt = 0; mt < 4; mt++)
        #pragma unroll
        for (int r = 0; r < 2; r++) {
            float v = Lp[mt][r];
            v += __shfl_xor_sync(0xffffffffu, v, 1);
            v += __shfl_xor_sync(0xffffffffu, v, 2);
            Lp[mt][r] = 1.f / v;
        }

    // store normalized output, pre-split bf16 hi/lo (k-pair packed)
    const int btk = bth >> 3;
    const int h   = bth & 7;
    #pragma unroll
    for (int mt = 0; mt < 4; mt++) {
        int r0 = warp * 64 + mt * 16 + lq;
        size_t t0 = ((size_t)(btk * SEQ + r0)) * KW3 + h * 8;
        size_t t1 = ((size_t)(btk * SEQ + r0 + 8)) * KW3 + h * 8;
        #pragma unroll
        for (int nc = 0; nc < 2; nc++) {
            unsigned hw, lw;
            split2(oacc[mt][nc][0] * Lp[mt][0], oacc[mt][nc][1] * Lp[mt][0], hw, lw);
            g_ah[t0 + nc * 4 + tq] = hw;
            g_al[t0 + nc * 4 + tq] = lw;
            split2(oacc[mt][nc][2] * Lp[mt][1], oacc[mt][nc][3] * Lp[mt][1], hw, lw);
            g_ah[t1 + nc * 4 + tq] = hw;
            g_al[t1 + nc * 4 + tq] = lw;
        }
    }
}

// ---------------------------------------------------------------------------
// K3: output projection via bf16x3 mma (unchanged, proven).
// ---------------------------------------------------------------------------
__global__ void __launch_bounds__(256, 2)
out_kernel(const float* __restrict__ bo, float* __restrict__ out)
{
    __shared__ __align__(16) unsigned SAh[128 * PITCH];
    __shared__ __align__(16) unsigned SAl[128 * PITCH];
    __shared__ __align__(16) unsigned SBh[128 * PITCH];
    __shared__ __align__(16) unsigned SBl[128 * PITCH];

    const int mblk = blockIdx.x;
    const int tid  = threadIdx.x;
    const int lane = tid & 31;
    const int warp = tid >> 5;
    const int wm = warp >> 1;
    const int wn = warp & 1;
    const int lq = lane >> 2;
    const int tq = lane & 3;
    const int m0 = mblk * 128;

    const int ar  = tid >> 1;
    const int ahf = tid & 1;
    const int bn  = tid & 127;
    const int bhf = tid >> 7;

    float acc[2][8][4];
    #pragma unroll
    for (int mt = 0; mt < 2; mt++)
        #pragma unroll
        for (int nt = 0; nt < 8; nt++)
            #pragma unroll
            for (int i = 0; i < 4; i++) acc[mt][nt][i] = 0.f;

    const int NT = DM / 16;   // 8

    uint4 pah = *(const uint4*)(g_ah + (size_t)(m0 + ar) * KW3 + ahf * 4);
    uint4 pal = *(const uint4*)(g_al + (size_t)(m0 + ar) * KW3 + ahf * 4);
    uint4 pbh = *(const uint4*)(g_WoTh + (size_t)bn * KW3 + bhf * 4);
    uint4 pbl = *(const uint4*)(g_WoTl + (size_t)bn * KW3 + bhf * 4);

    for (int kt = 0; kt < NT; ++kt) {
        __syncthreads();
        {
            int base = ar * PITCH + ahf * 4;
            SAh[base + 0] = pah.x; SAh[base + 1] = pah.y; SAh[base + 2] = pah.z; SAh[base + 3] = pah.w;
            SAl[base + 0] = pal.x; SAl[base + 1] = pal.y; SAl[base + 2] = pal.z; SAl[base + 3] = pal.w;
            int bb = bn * PITCH + bhf * 4;
            SBh[bb + 0] = pbh.x; SBh[bb + 1] = pbh.y; SBh[bb + 2] = pbh.z; SBh[bb + 3] = pbh.w;
            SBl[bb + 0] = pbl.x; SBl[bb + 1] = pbl.y; SBl[bb + 2] = pbl.z; SBl[bb + 3] = pbl.w;
        }
        __syncthreads();

        if (kt + 1 < NT) {
            pah = *(const uint4*)(g_ah + (size_t)(m0 + ar) * KW3 + (kt + 1) * 8 + ahf * 4);
            pal = *(const uint4*)(g_al + (size_t)(m0 + ar) * KW3 + (kt + 1) * 8 + ahf * 4);
            pbh = *(const uint4*)(g_WoTh + (size_t)bn * KW3 + (kt + 1) * 8 + bhf * 4);
            pbl = *(const uint4*)(g_WoTl + (size_t)bn * KW3 + (kt + 1) * 8 + bhf * 4);
        }

        unsigned ah[2][4], al[2][4];
        #pragma unroll
        for (int mt = 0; mt < 2; mt++) {
            int rb = wm * 32 + mt * 16 + lq;
            ah[mt][0] = SAh[rb * PITCH + tq];
            ah[mt][1] = SAh[(rb + 8) * PITCH + tq];
            ah[mt][2] = SAh[rb * PITCH + 4 + tq];
            ah[mt][3] = SAh[(rb + 8) * PITCH + 4 + tq];
            al[mt][0] = SAl[rb * PITCH + tq];
            al[mt][1] = SAl[(rb + 8) * PITCH + tq];
            al[mt][2] = SAl[rb * PITCH + 4 + tq];
            al[mt][3] = SAl[(rb + 8) * PITCH + 4 + tq];
        }

        #pragma unroll
        for (int nt = 0; nt < 8; nt++) {
            int nb = wn * 64 + nt * 8 + lq;
            unsigned bh[2], bl[2];
            bh[0] = SBh[nb * PITCH + tq];
            bh[1] = SBh[nb * PITCH + 4 + tq];
            bl[0] = SBl[nb * PITCH + tq];
            bl[1] = SBl[nb * PITCH + 4 + tq];
            #pragma unroll
            for (int mt = 0; mt < 2; mt++) {
                mma16816(acc[mt][nt], ah[mt], bh);
                mma16816(acc[mt][nt], al[mt], bh);
                mma16816(acc[mt][nt], ah[mt], bl);
            }
        }
    }

    #pragma unroll
    for (int mt = 0; mt < 2; mt++) {
        int r0 = m0 + wm * 32 + mt * 16 + lq;
        #pragma unroll
        for (int nt = 0; nt < 8; nt++) {
            int c = wn * 64 + nt * 8 + tq * 2;
            float b0 = bo[c], b1 = bo[c + 1];
            float2 v0, v1;
            v0.x = fmaxf(acc[mt][nt][0] + b0, 0.f);
            v0.y = fmaxf(acc[mt][nt][1] + b1, 0.f);
            v1.x = fmaxf(acc[mt][nt][2] + b0, 0.f);
            v1.y = fmaxf(acc[mt][nt][3] + b1, 0.f);
            *(float2*)&out[(size_t)r0 * DM + c]       = v0;
            *(float2*)&out[(size_t)(r0 + 8) * DM + c] = v1;
        }
    }
}

// ---------------------------------------------------------------------------
extern "C" void kernel_launch(void* const* d_in, const int* in_sizes, int n_in,
                              void* d_out, int out_size)
{
    const float* X   = (const float*)d_in[0];
    const float* STE = (const float*)d_in[1];
    const float* Wq  = (const float*)d_in[2];
    const float* bq  = (const float*)d_in[3];
    const float* Wk  = (const float*)d_in[4];
    const float* bk  = (const float*)d_in[5];
    const float* Wv  = (const float*)d_in[6];
    const float* bv  = (const float*)d_in[7];
    const float* Wo  = (const float*)d_in[8];
    const float* bo  = (const float*)d_in[9];
    float* out = (float*)d_out;

    wsplit_kernel<<<(3 * DM * KW + DM * KW3 + 255) / 256, 256>>>(Wq, Wk, Wv, Wo);
    qkv_kernel<<<dim3(NTOK / 128, 3), 256>>>(X, STE, bq, bk, bv);
    attn_kernel<<<BT * NH, 256>>>();
    out_kernel<<<NTOK / 128, 256>>>(bo, out);
}

// round 12
// speedup vs baseline: 2.2867x; 1.0443x over previous
#include <cuda_runtime.h>
#include <cuda_bf16.h>
#include <cstddef>
#include <cstdint>

// ---------------------------------------------------------------------------
// SpatialAttention on GB300 (harness targets sm_103 baseline: NO tcgen05).
//  K0a: wsplit — pre-split/transpose weights to bf16 hi/lo packed words
//  K0b: hsplit — pre-split H=concat(X,STE) to bf16 hi/lo packed words
//  K1 : qkv    — bf16x3 warp-mma GEMM (ldmatrix frags, double-buffered),
//                relu+bias, writes packed q/k hi/lo + v (head-major)
//  K2 : attn   — tensor-core flash attention, no-max softmax (proven R8)
//  K3 : out    — bf16x3 warp-mma GEMM (ldmatrix, double-buffered) -> f32 out
// ---------------------------------------------------------------------------

#define NTOK   49152
#define BT     96
#define SEQ    512
#define DM     128
#define DH     16
#define NH     8
#define KDIM   384
#define KW     (KDIM/2)   // 192 k-pair words per row
#define KW3    (DM/2)     // 64
#define PITCH  12         // smem pitch in words: 16B-aligned, ldmatrix conflict-free

// pre-split transposed weights: word = (bf16(k even) low | bf16(k odd) high)
__device__ unsigned g_WTh[3 * DM * KW];
__device__ unsigned g_WTl[3 * DM * KW];
__device__ unsigned g_WoTh[DM * KW3];
__device__ unsigned g_WoTl[DM * KW3];
// pre-split H: [tok][192 kpair words]
__device__ unsigned g_Hh[(size_t)NTOK * KW];
__device__ unsigned g_Hl[(size_t)NTOK * KW];
// q/k/v head-major, d-pair packed bf16 words: [(bt*8+h)*512 + n][8]
__device__ unsigned g_qh[BT * NH * SEQ * 8];
__device__ unsigned g_ql[BT * NH * SEQ * 8];
__device__ unsigned g_kh[BT * NH * SEQ * 8];
__device__ unsigned g_kl[BT * NH * SEQ * 8];
__device__ unsigned g_vh[BT * NH * SEQ * 8];
// attention output, pre-split bf16 hi/lo, k-pair packed: [tok][64 words]
__device__ unsigned g_ah[(size_t)NTOK * KW3];
__device__ unsigned g_al[(size_t)NTOK * KW3];

// ---------------------------------------------------------------------------
// helpers
// ---------------------------------------------------------------------------
__device__ __forceinline__ unsigned packbf(float lo, float hi) {
    unsigned r;
    asm("cvt.rn.satfinite.bf16x2.f32 %0, %1, %2;" : "=r"(r) : "f"(hi), "f"(lo));
    return r;
}

__device__ __forceinline__ void split2(float x, float y, unsigned& h, unsigned& l) {
    h = packbf(x, y);
    float hx = __uint_as_float(h << 16);
    float hy = __uint_as_float(h & 0xffff0000u);
    l = packbf(x - hx, y - hy);
}

__device__ __forceinline__ unsigned prmt(unsigned a, unsigned b, unsigned sel) {
    unsigned r;
    asm("prmt.b32 %0,%1,%2,%3;" : "=r"(r) : "r"(a), "r"(b), "r"(sel));
    return r;
}

__device__ __forceinline__ void mma16816(float c[4], const unsigned a[4], const unsigned b[2]) {
    asm volatile(
        "mma.sync.aligned.m16n8k16.row.col.f32.bf16.bf16.f32 "
        "{%0,%1,%2,%3},{%4,%5,%6,%7},{%8,%9},{%0,%1,%2,%3};"
        : "+f"(c[0]), "+f"(c[1]), "+f"(c[2]), "+f"(c[3])
        : "r"(a[0]), "r"(a[1]), "r"(a[2]), "r"(a[3]), "r"(b[0]), "r"(b[1]));
}

__device__ __forceinline__ void ldsm_x4(unsigned r[4], uint32_t saddr) {
    asm volatile("ldmatrix.sync.aligned.m8n8.x4.shared.b16 {%0,%1,%2,%3}, [%4];"
                 : "=r"(r[0]), "=r"(r[1]), "=r"(r[2]), "=r"(r[3]) : "r"(saddr));
}

__device__ __forceinline__ float4 ldH(const float* __restrict__ X,
                                      const float* __restrict__ STE,
                                      int row, int col)
{
    return (col < DM) ? *(const float4*)(X + (size_t)row * DM + col)
                      : *(const float4*)(STE + (size_t)row * 256 + (col - DM));
}

// ---------------------------------------------------------------------------
// K0a: weight pre-split
// ---------------------------------------------------------------------------
__global__ void wsplit_kernel(const float* __restrict__ Wq, const float* __restrict__ Wk,
                              const float* __restrict__ Wv, const float* __restrict__ Wo)
{
    int idx = blockIdx.x * 256 + threadIdx.x;
    if (idx < 3 * DM * KW) {
        int mat = idx / (DM * KW);
        int rem = idx % (DM * KW);
        int n = rem / KW;
        int kp = rem % KW;
        const float* W = (mat == 0) ? Wq : (mat == 1) ? Wk : Wv;
        unsigned h, l;
        split2(W[(2 * kp) * DM + n], W[(2 * kp + 1) * DM + n], h, l);
        g_WTh[idx] = h;
        g_WTl[idx] = l;
    } else {
        int j = idx - 3 * DM * KW;
        if (j < DM * KW3) {
            int n = j / KW3;
            int kp = j % KW3;
            unsigned h, l;
            split2(Wo[(2 * kp) * DM + n], Wo[(2 * kp + 1) * DM + n], h, l);
            g_WoTh[j] = h;
            g_WoTl[j] = l;
        }
    }
}

// ---------------------------------------------------------------------------
// K0b: H pre-split. One thread = 8 consecutive H columns of one token.
// ---------------------------------------------------------------------------
__global__ void hsplit_kernel(const float* __restrict__ X, const float* __restrict__ STE)
{
    int idx = blockIdx.x * 256 + threadIdx.x;     // exact: NTOK*48 threads
    int tok = idx / 48;
    int q = idx - tok * 48;
    int k0 = q * 8;
    float4 a = ldH(X, STE, tok, k0);
    float4 b = ldH(X, STE, tok, k0 + 4);
    unsigned h0, l0, h1, l1, h2, l2, h3, l3;
    split2(a.x, a.y, h0, l0);
    split2(a.z, a.w, h1, l1);
    split2(b.x, b.y, h2, l2);
    split2(b.z, b.w, h3, l3);
    *(uint4*)(g_Hh + (size_t)tok * KW + q * 4) = make_uint4(h0, h1, h2, h3);
    *(uint4*)(g_Hl + (size_t)tok * KW + q * 4) = make_uint4(l0, l1, l2, l3);
}

// ---------------------------------------------------------------------------
// K1: qkv projection. Block tile 128x128, 8 warps (warp 32x64), K=16/step,
// 24 steps, double-buffered, ldmatrix fragment loads, uint4 staging.
// ---------------------------------------------------------------------------
__global__ void __launch_bounds__(256, 2)
qkv_kernel(const float* __restrict__ bq, const float* __restrict__ bk,
           const float* __restrict__ bv)
{
    __shared__ __align__(16) unsigned SAh[2][128 * PITCH];
    __shared__ __align__(16) unsigned SAl[2][128 * PITCH];
    __shared__ __align__(16) unsigned SBh[2][128 * PITCH];
    __shared__ __align__(16) unsigned SBl[2][128 * PITCH];

    const int mblk = blockIdx.x;
    const int mat  = blockIdx.y;
    const float* bias = (mat == 0) ? bq : (mat == 1) ? bk : bv;
    const unsigned* WTh = g_WTh + (size_t)mat * DM * KW;
    const unsigned* WTl = g_WTl + (size_t)mat * DM * KW;
    unsigned* outh = (mat == 0) ? g_qh : (mat == 1) ? g_kh : g_vh;
    unsigned* outl = (mat == 0) ? g_ql : g_kl;   // only used when mat<2

    const int tid  = threadIdx.x;
    const int lane = tid & 31;
    const int warp = tid >> 5;
    const int wm = warp >> 1;
    const int wn = warp & 1;
    const int lq = lane >> 2;
    const int tq = lane & 3;
    const int m0 = mblk * 128;

    const int ar  = tid >> 1;
    const int ahf = tid & 1;
    const int bn  = tid & 127;
    const int bhf = tid >> 7;

    // ldmatrix per-lane word offsets (constant across iterations)
    const int a_woff = (wm * 32 + (lane & 15)) * PITCH + (lane >> 4) * 4;
    const int g      = lane >> 3;
    const int b_row  = (g >> 1) * 8 + (lane & 7);
    const int b_word = (g & 1) * 4;

    const uint32_t sAh0 = (uint32_t)__cvta_generic_to_shared(&SAh[0][0]);
    const uint32_t sAl0 = (uint32_t)__cvta_generic_to_shared(&SAl[0][0]);
    const uint32_t sBh0 = (uint32_t)__cvta_generic_to_shared(&SBh[0][0]);
    const uint32_t sBl0 = (uint32_t)__cvta_generic_to_shared(&SBl[0][0]);
    const uint32_t bufstride = 128 * PITCH * 4;

    float acc[2][8][4];
    #pragma unroll
    for (int mt = 0; mt < 2; mt++)
        #pragma unroll
        for (int nt = 0; nt < 8; nt++)
            #pragma unroll
            for (int i = 0; i < 4; i++) acc[mt][nt][i] = 0.f;

    const int NT = KDIM / 16;   // 24

    uint4 pah = *(const uint4*)(g_Hh + (size_t)(m0 + ar) * KW + ahf * 4);
    uint4 pal = *(const uint4*)(g_Hl + (size_t)(m0 + ar) * KW + ahf * 4);
    uint4 pbh = *(const uint4*)(WTh + (size_t)bn * KW + bhf * 4);
    uint4 pbl = *(const uint4*)(WTl + (size_t)bn * KW + bhf * 4);

    // stage buffer 0
    *(uint4*)&SAh[0][ar * PITCH + ahf * 4] = pah;
    *(uint4*)&SAl[0][ar * PITCH + ahf * 4] = pal;
    *(uint4*)&SBh[0][bn * PITCH + bhf * 4] = pbh;
    *(uint4*)&SBl[0][bn * PITCH + bhf * 4] = pbl;
    __syncthreads();

    for (int kt = 0; kt < NT; ++kt) {
        const int cur = kt & 1, nxt = cur ^ 1;
        if (kt + 1 < NT) {
            pah = *(const uint4*)(g_Hh + (size_t)(m0 + ar) * KW + (kt + 1) * 8 + ahf * 4);
            pal = *(const uint4*)(g_Hl + (size_t)(m0 + ar) * KW + (kt + 1) * 8 + ahf * 4);
            pbh = *(const uint4*)(WTh + (size_t)bn * KW + (kt + 1) * 8 + bhf * 4);
            pbl = *(const uint4*)(WTl + (size_t)bn * KW + (kt + 1) * 8 + bhf * 4);
        }

        unsigned ah[2][4], al[2][4];
        ldsm_x4(ah[0], sAh0 + cur * bufstride + a_woff * 4);
        ldsm_x4(ah[1], sAh0 + cur * bufstride + (a_woff + 16 * PITCH) * 4);
        ldsm_x4(al[0], sAl0 + cur * bufstride + a_woff * 4);
        ldsm_x4(al[1], sAl0 + cur * bufstride + (a_woff + 16 * PITCH) * 4);

        unsigned bh[4][4], bl[4][4];
        #pragma unroll
        for (int p = 0; p < 4; p++) {
            int boff = ((wn * 64 + p * 16 + b_row) * PITCH + b_word) * 4;
            ldsm_x4(bh[p], sBh0 + cur * bufstride + boff);
            ldsm_x4(bl[p], sBl0 + cur * bufstride + boff);
        }

        #pragma unroll
        for (int nt = 0; nt < 8; nt++) {
            const unsigned* bhp = &bh[nt >> 1][(nt & 1) * 2];
            const unsigned* blp = &bl[nt >> 1][(nt & 1) * 2];
            #pragma unroll
            for (int mt = 0; mt < 2; mt++) {
                mma16816(acc[mt][nt], ah[mt], bhp);   // hi*hi
                mma16816(acc[mt][nt], al[mt], bhp);   // lo*hi
                mma16816(acc[mt][nt], ah[mt], blp);   // hi*lo
            }
        }

        if (kt + 1 < NT) {
            *(uint4*)&SAh[nxt][ar * PITCH + ahf * 4] = pah;
            *(uint4*)&SAl[nxt][ar * PITCH + ahf * 4] = pal;
            *(uint4*)&SBh[nxt][bn * PITCH + bhf * 4] = pbh;
            *(uint4*)&SBl[nxt][bn * PITCH + bhf * 4] = pbl;
        }
        __syncthreads();
    }

    // epilogue: relu(acc+bias), split bf16 hi/lo, head-major d-pair words
    #pragma unroll
    for (int mt = 0; mt < 2; mt++) {
        int r0 = m0 + wm * 32 + mt * 16 + lq;
        int btk = r0 >> 9;
        int n0  = r0 & 511;
        #pragma unroll
        for (int nt = 0; nt < 8; nt++) {
            int c = wn * 64 + nt * 8 + tq * 2;
            int h = c >> 4, dp = (c & 15) >> 1;
            float b0 = bias[c], b1 = bias[c + 1];
            size_t w0 = ((size_t)(btk * NH + h) * SEQ + n0) * 8 + dp;
            size_t w1 = ((size_t)(btk * NH + h) * SEQ + n0 + 8) * 8 + dp;
            unsigned hw, lw;
            split2(fmaxf(acc[mt][nt][0] + b0, 0.f), fmaxf(acc[mt][nt][1] + b1, 0.f), hw, lw);
            outh[w0] = hw;
            if (mat < 2) outl[w0] = lw;
            split2(fmaxf(acc[mt][nt][2] + b0, 0.f), fmaxf(acc[mt][nt][3] + b1, 0.f), hw, lw);
            outh[w1] = hw;
            if (mat < 2) outl[w1] = lw;
        }
    }
}

// ---------------------------------------------------------------------------
// K2: tensor-core attention (unchanged from R8, proven).
// ---------------------------------------------------------------------------
__device__ __forceinline__ int sVidx(int d, int kp) {
    return d * 256 + (kp ^ ((d & 7) << 2));
}

__global__ void __launch_bounds__(256, 2)
attn_kernel()
{
    __shared__ unsigned sKh[512 * 8];
    __shared__ unsigned sKl[512 * 8];
    __shared__ unsigned sV[16 * 256];

    const int bth = blockIdx.x;
    const int tid = threadIdx.x;
    const int lane = tid & 31;
    const int warp = tid >> 5;
    const int lq = lane >> 2;
    const int tq = lane & 3;
    const size_t kvbase = (size_t)bth * (SEQ * 8);

    {
        const uint4* gh = (const uint4*)(g_kh + kvbase);
        const uint4* gl = (const uint4*)(g_kl + kvbase);
        uint4* sh = (uint4*)sKh;
        uint4* sl = (uint4*)sKl;
        #pragma unroll
        for (int j = 0; j < 4; j++) {
            sh[tid + j * 256] = gh[tid + j * 256];
            sl[tid + j * 256] = gl[tid + j * 256];
        }
    }
    {
        const uint4* gv = (const uint4*)(g_vh + kvbase);
        int kp = tid;
        uint4 a0 = gv[kp * 4 + 0];
        uint4 a1 = gv[kp * 4 + 1];
        uint4 b0 = gv[kp * 4 + 2];
        uint4 b1 = gv[kp * 4 + 3];
        unsigned ia[8] = {a0.x, a0.y, a0.z, a0.w, a1.x, a1.y, a1.z, a1.w};
        unsigned ib[8] = {b0.x, b0.y, b0.z, b0.w, b1.x, b1.y, b1.z, b1.w};
        #pragma unroll
        for (int dp = 0; dp < 8; dp++) {
            sV[sVidx(2 * dp,     kp)] = prmt(ia[dp], ib[dp], 0x5410);
            sV[sVidx(2 * dp + 1, kp)] = prmt(ia[dp], ib[dp], 0x7632);
        }
    }
    __syncthreads();

    const unsigned* qh = g_qh + kvbase;
    const unsigned* ql = g_ql + kvbase;
    unsigned qah[4][4], qal[4][4];
    #pragma unroll
    for (int mt = 0; mt < 4; mt++) {
        int r = warp * 64 + mt * 16 + lq;
        qah[mt][0] = qh[(size_t)r * 8 + tq];
        qah[mt][1] = qh[(size_t)(r + 8) * 8 + tq];
        qah[mt][2] = qh[(size_t)r * 8 + tq + 4];
        qah[mt][3] = qh[(size_t)(r + 8) * 8 + tq + 4];
        qal[mt][0] = ql[(size_t)r * 8 + tq];
        qal[mt][1] = ql[(size_t)(r + 8) * 8 + tq];
        qal[mt][2] = ql[(size_t)r * 8 + tq + 4];
        qal[mt][3] = ql[(size_t)(r + 8) * 8 + tq + 4];
    }

    float oacc[4][2][4];
    float Lp[4][2];
    #pragma unroll
    for (int mt = 0; mt < 4; mt++) {
        Lp[mt][0] = 0.f; Lp[mt][1] = 0.f;
        #pragma unroll
        for (int nc = 0; nc < 2; nc++)
            #pragma unroll
            for (int i = 0; i < 4; i++) oacc[mt][nc][i] = 0.f;
    }

    for (int c = 0; c < 32; c++) {
        unsigned bh[2][2], bl[2][2], bv[2][2];
        #pragma unroll
        for (int nc = 0; nc < 2; nc++) {
            int kb = c * 16 + nc * 8 + lq;
            bh[nc][0] = sKh[kb * 8 + tq];
            bh[nc][1] = sKh[kb * 8 + tq + 4];
            bl[nc][0] = sKl[kb * 8 + tq];
            bl[nc][1] = sKl[kb * 8 + tq + 4];
            bv[nc][0] = sV[sVidx(nc * 8 + lq, c * 8 + tq)];
            bv[nc][1] = sV[sVidx(nc * 8 + lq, c * 8 + tq + 4)];
        }
        #pragma unroll
        for (int mt = 0; mt < 4; mt++) {
            float s[2][4];
            #pragma unroll
            for (int nc = 0; nc < 2; nc++) {
                #pragma unroll
                for (int i = 0; i < 4; i++) s[nc][i] = 0.f;
                mma16816(s[nc], qah[mt], bh[nc]);
                mma16816(s[nc], qal[mt], bh[nc]);
                mma16816(s[nc], qah[mt], bl[nc]);
                #pragma unroll
                for (int i = 0; i < 4; i++)
                    s[nc][i] = __expf(fmaf(s[nc][i], 0.25f, -8.0f));
            }
            Lp[mt][0] += s[0][0] + s[0][1] + s[1][0] + s[1][1];
            Lp[mt][1] += s[0][2] + s[0][3] + s[1][2] + s[1][3];
            unsigned pA[4] = { packbf(s[0][0], s[0][1]), packbf(s[0][2], s[0][3]),
                               packbf(s[1][0], s[1][1]), packbf(s[1][2], s[1][3]) };
            mma16816(oacc[mt][0], pA, bv[0]);
            mma16816(oacc[mt][1], pA, bv[1]);
        }
    }

    #pragma unroll
    for (int mt = 0; mt < 4; mt++)
        #pragma unroll
        for (int r = 0; r < 2; r++) {
            float v = Lp[mt][r];
            v += __shfl_xor_sync(0xffffffffu, v, 1);
            v += __shfl_xor_sync(0xffffffffu, v, 2);
            Lp[mt][r] = 1.f / v;
        }

    const int btk = bth >> 3;
    const int h   = bth & 7;
    #pragma unroll
    for (int mt = 0; mt < 4; mt++) {
        int r0 = warp * 64 + mt * 16 + lq;
        size_t t0 = ((size_t)(btk * SEQ + r0)) * KW3 + h * 8;
        size_t t1 = ((size_t)(btk * SEQ + r0 + 8)) * KW3 + h * 8;
        #pragma unroll
        for (int nc = 0; nc < 2; nc++) {
            unsigned hw, lw;
            split2(oacc[mt][nc][0] * Lp[mt][0], oacc[mt][nc][1] * Lp[mt][0], hw, lw);
            g_ah[t0 + nc * 4 + tq] = hw;
            g_al[t0 + nc * 4 + tq] = lw;
            split2(oacc[mt][nc][2] * Lp[mt][1], oacc[mt][nc][3] * Lp[mt][1], hw, lw);
            g_ah[t1 + nc * 4 + tq] = hw;
            g_al[t1 + nc * 4 + tq] = lw;
        }
    }
}

// ---------------------------------------------------------------------------
// K3: output projection, same structure as K1 (NT=8), double-buffered+ldmatrix.
// ---------------------------------------------------------------------------
__global__ void __launch_bounds__(256, 2)
out_kernel(const float* __restrict__ bo, float* __restrict__ out)
{
    __shared__ __align__(16) unsigned SAh[2][128 * PITCH];
    __shared__ __align__(16) unsigned SAl[2][128 * PITCH];
    __shared__ __align__(16) unsigned SBh[2][128 * PITCH];
    __shared__ __align__(16) unsigned SBl[2][128 * PITCH];

    const int mblk = blockIdx.x;
    const int tid  = threadIdx.x;
    const int lane = tid & 31;
    const int warp = tid >> 5;
    const int wm = warp >> 1;
    const int wn = warp & 1;
    const int lq = lane >> 2;
    const int tq = lane & 3;
    const int m0 = mblk * 128;

    const int ar  = tid >> 1;
    const int ahf = tid & 1;
    const int bn  = tid & 127;
    const int bhf = tid >> 7;

    const int a_woff = (wm * 32 + (lane & 15)) * PITCH + (lane >> 4) * 4;
    const int g      = lane >> 3;
    const int b_row  = (g >> 1) * 8 + (lane & 7);
    const int b_word = (g & 1) * 4;

    const uint32_t sAh0 = (uint32_t)__cvta_generic_to_shared(&SAh[0][0]);
    const uint32_t sAl0 = (uint32_t)__cvta_generic_to_shared(&SAl[0][0]);
    const uint32_t sBh0 = (uint32_t)__cvta_generic_to_shared(&SBh[0][0]);
    const uint32_t sBl0 = (uint32_t)__cvta_generic_to_shared(&SBl[0][0]);
    const uint32_t bufstride = 128 * PITCH * 4;

    float acc[2][8][4];
    #pragma unroll
    for (int mt = 0; mt < 2; mt++)
        #pragma unroll
        for (int nt = 0; nt < 8; nt++)
            #pragma unroll
            for (int i = 0; i < 4; i++) acc[mt][nt][i] = 0.f;

    const int NT = DM / 16;   // 8

    uint4 pah = *(const uint4*)(g_ah + (size_t)(m0 + ar) * KW3 + ahf * 4);
    uint4 pal = *(const uint4*)(g_al + (size_t)(m0 + ar) * KW3 + ahf * 4);
    uint4 pbh = *(const uint4*)(g_WoTh + (size_t)bn * KW3 + bhf * 4);
    uint4 pbl = *(const uint4*)(g_WoTl + (size_t)bn * KW3 + bhf * 4);

    *(uint4*)&SAh[0][ar * PITCH + ahf * 4] = pah;
    *(uint4*)&SAl[0][ar * PITCH + ahf * 4] = pal;
    *(uint4*)&SBh[0][bn * PITCH + bhf * 4] = pbh;
    *(uint4*)&SBl[0][bn * PITCH + bhf * 4] = pbl;
    __syncthreads();

    for (int kt = 0; kt < NT; ++kt) {
        const int cur = kt & 1, nxt = cur ^ 1;
        if (kt + 1 < NT) {
            pah = *(const uint4*)(g_ah + (size_t)(m0 + ar) * KW3 + (kt + 1) * 8 + ahf * 4);
            pal = *(const uint4*)(g_al + (size_t)(m0 + ar) * KW3 + (kt + 1) * 8 + ahf * 4);
            pbh = *(const uint4*)(g_WoTh + (size_t)bn * KW3 + (kt + 1) * 8 + bhf * 4);
            pbl = *(const uint4*)(g_WoTl + (size_t)bn * KW3 + (kt + 1) * 8 + bhf * 4);
        }

        unsigned ah[2][4], al[2][4];
        ldsm_x4(ah[0], sAh0 + cur * bufstride + a_woff * 4);
        ldsm_x4(ah[1], sAh0 + cur * bufstride + (a_woff + 16 * PITCH) * 4);
        ldsm_x4(al[0], sAl0 + cur * bufstride + a_woff * 4);
        ldsm_x4(al[1], sAl0 + cur * bufstride + (a_woff + 16 * PITCH) * 4);

        unsigned bh[4][4], bl[4][4];
        #pragma unroll
        for (int p = 0; p < 4; p++) {
            int boff = ((wn * 64 + p * 16 + b_row) * PITCH + b_word) * 4;
            ldsm_x4(bh[p], sBh0 + cur * bufstride + boff);
            ldsm_x4(bl[p], sBl0 + cur * bufstride + boff);
        }

        #pragma unroll
        for (int nt = 0; nt < 8; nt++) {
            const unsigned* bhp = &bh[nt >> 1][(nt & 1) * 2];
            const unsigned* blp = &bl[nt >> 1][(nt & 1) * 2];
            #pragma unroll
            for (int mt = 0; mt < 2; mt++) {
                mma16816(acc[mt][nt], ah[mt], bhp);
                mma16816(acc[mt][nt], al[mt], bhp);
                mma16816(acc[mt][nt], ah[mt], blp);
            }
        }

        if (kt + 1 < NT) {
            *(uint4*)&SAh[nxt][ar * PITCH + ahf * 4] = pah;
            *(uint4*)&SAl[nxt][ar * PITCH + ahf * 4] = pal;
            *(uint4*)&SBh[nxt][bn * PITCH + bhf * 4] = pbh;
            *(uint4*)&SBl[nxt][bn * PITCH + bhf * 4] = pbl;
        }
        __syncthreads();
    }

    #pragma unroll
    for (int mt = 0; mt < 2; mt++) {
        int r0 = m0 + wm * 32 + mt * 16 + lq;
        #pragma unroll
        for (int nt = 0; nt < 8; nt++) {
            int c = wn * 64 + nt * 8 + tq * 2;
            float b0 = bo[c], b1 = bo[c + 1];
            float2 v0, v1;
            v0.x = fmaxf(acc[mt][nt][0] + b0, 0.f);
            v0.y = fmaxf(acc[mt][nt][1] + b1, 0.f);
            v1.x = fmaxf(acc[mt][nt][2] + b0, 0.f);
            v1.y = fmaxf(acc[mt][nt][3] + b1, 0.f);
            *(float2*)&out[(size_t)r0 * DM + c]       = v0;
            *(float2*)&out[(size_t)(r0 + 8) * DM + c] = v1;
        }
    }
}

// ---------------------------------------------------------------------------
extern "C" void kernel_launch(void* const* d_in, const int* in_sizes, int n_in,
                              void* d_out, int out_size)
{
    const float* X   = (const float*)d_in[0];
    const float* STE = (const float*)d_in[1];
    const float* Wq  = (const float*)d_in[2];
    const float* bq  = (const float*)d_in[3];
    const float* Wk  = (const float*)d_in[4];
    const float* bk  = (const float*)d_in[5];
    const float* Wv  = (const float*)d_in[6];
    const float* bv  = (const float*)d_in[7];
    const float* Wo  = (const float*)d_in[8];
    const float* bo  = (const float*)d_in[9];
    float* out = (float*)d_out;

    wsplit_kernel<<<(3 * DM * KW + DM * KW3 + 255) / 256, 256>>>(Wq, Wk, Wv, Wo);
    hsplit_kernel<<<NTOK * 48 / 256, 256>>>(X, STE);
    qkv_kernel<<<dim3(NTOK / 128, 3), 256>>>(bq, bk, bv);
    attn_kernel<<<BT * NH, 256>>>();
    out_kernel<<<NTOK / 128, 256>>>(bo, out);
}

// round 13
// speedup vs baseline: 2.5844x; 1.1302x over previous
#include <cuda_runtime.h>
#include <cuda_bf16.h>
#include <cstddef>
#include <cstdint>

// ---------------------------------------------------------------------------
// SpatialAttention on GB300 (harness targets sm_103 baseline: NO tcgen05).
//  K0a: wsplit — pre-split/transpose weights to bf16 hi/lo packed words
//  K0b: hsplit — pre-split H=concat(X,STE) to bf16 hi/lo packed words
//  K1 : qkv    — bf16x3 warp-mma GEMM, 4-stage cp.async pipeline, ldmatrix
//  K2 : attn   — tensor-core flash attention, no-max softmax, fused ex2
//  K3 : out    — bf16x3 warp-mma GEMM, 4-stage cp.async pipeline -> f32 out
// ---------------------------------------------------------------------------

#define NTOK   49152
#define BT     96
#define SEQ    512
#define DM     128
#define DH     16
#define NH     8
#define KDIM   384
#define KW     (KDIM/2)   // 192 k-pair words per row
#define KW3    (DM/2)     // 64
#define PITCH  12         // smem pitch in words: 16B-aligned, ldmatrix conflict-free

// cp.async pipeline geometry (shared by qkv and out kernels)
#define NSTG      4
#define ARR_BYTES (128 * PITCH * 4)      // 6144 B per array
#define STG_BYTES (4 * ARR_BYTES)        // Ah|Al|Bh|Bl = 24576 B per stage
#define A_H_OFF   0
#define A_L_OFF   (1 * ARR_BYTES)
#define B_H_OFF   (2 * ARR_BYTES)
#define B_L_OFF   (3 * ARR_BYTES)
#define GEMM_SMEM (NSTG * STG_BYTES)     // 98304 B

// pre-split transposed weights: word = (bf16(k even) low | bf16(k odd) high)
__device__ unsigned g_WTh[3 * DM * KW];
__device__ unsigned g_WTl[3 * DM * KW];
__device__ unsigned g_WoTh[DM * KW3];
__device__ unsigned g_WoTl[DM * KW3];
// pre-split H: [tok][192 kpair words]
__device__ unsigned g_Hh[(size_t)NTOK * KW];
__device__ unsigned g_Hl[(size_t)NTOK * KW];
// q/k/v head-major, d-pair packed bf16 words: [(bt*8+h)*512 + n][8]
__device__ unsigned g_qh[BT * NH * SEQ * 8];
__device__ unsigned g_ql[BT * NH * SEQ * 8];
__device__ unsigned g_kh[BT * NH * SEQ * 8];
__device__ unsigned g_kl[BT * NH * SEQ * 8];
__device__ unsigned g_vh[BT * NH * SEQ * 8];
// attention output, pre-split bf16 hi/lo, k-pair packed: [tok][64 words]
__device__ unsigned g_ah[(size_t)NTOK * KW3];
__device__ unsigned g_al[(size_t)NTOK * KW3];

// ---------------------------------------------------------------------------
// helpers
// ---------------------------------------------------------------------------
__device__ __forceinline__ unsigned packbf(float lo, float hi) {
    unsigned r;
    asm("cvt.rn.satfinite.bf16x2.f32 %0, %1, %2;" : "=r"(r) : "f"(hi), "f"(lo));
    return r;
}

__device__ __forceinline__ void split2(float x, float y, unsigned& h, unsigned& l) {
    h = packbf(x, y);
    float hx = __uint_as_float(h << 16);
    float hy = __uint_as_float(h & 0xffff0000u);
    l = packbf(x - hx, y - hy);
}

__device__ __forceinline__ unsigned prmt(unsigned a, unsigned b, unsigned sel) {
    unsigned r;
    asm("prmt.b32 %0,%1,%2,%3;" : "=r"(r) : "r"(a), "r"(b), "r"(sel));
    return r;
}

__device__ __forceinline__ void mma16816(float c[4], const unsigned a[4], const unsigned b[2]) {
    asm volatile(
        "mma.sync.aligned.m16n8k16.row.col.f32.bf16.bf16.f32 "
        "{%0,%1,%2,%3},{%4,%5,%6,%7},{%8,%9},{%0,%1,%2,%3};"
        : "+f"(c[0]), "+f"(c[1]), "+f"(c[2]), "+f"(c[3])
        : "r"(a[0]), "r"(a[1]), "r"(a[2]), "r"(a[3]), "r"(b[0]), "r"(b[1]));
}

__device__ __forceinline__ void ldsm_x4(unsigned r[4], uint32_t saddr) {
    asm volatile("ldmatrix.sync.aligned.m8n8.x4.shared.b16 {%0,%1,%2,%3}, [%4];"
                 : "=r"(r[0]), "=r"(r[1]), "=r"(r[2]), "=r"(r[3]) : "r"(saddr));
}

// exp2 approx (same HW unit __expf lowers to; constants fold scale+shift)
__device__ __forceinline__ float ex2a(float x) {
    float r;
    asm("ex2.approx.f32 %0, %1;" : "=f"(r) : "f"(x));
    return r;
}
#define EXP_C1 0.36067376022224085f    // log2(e)/4
#define EXP_C2 (-11.541560327111707f)  // -8*log2(e)

#define CP_ASYNC16(dst, src) \
    asm volatile("cp.async.cg.shared.global [%0], [%1], 16;" :: "r"(dst), "l"(src))
#define CP_COMMIT() asm volatile("cp.async.commit_group;" ::: "memory")
#define CP_WAIT(n)  asm volatile("cp.async.wait_group %0;" :: "n"(n) : "memory")

__device__ __forceinline__ float4 ldH(const float* __restrict__ X,
                                      const float* __restrict__ STE,
                                      int row, int col)
{
    return (col < DM) ? *(const float4*)(X + (size_t)row * DM + col)
                      : *(const float4*)(STE + (size_t)row * 256 + (col - DM));
}

// ---------------------------------------------------------------------------
// K0a: weight pre-split
// ---------------------------------------------------------------------------
__global__ void wsplit_kernel(const float* __restrict__ Wq, const float* __restrict__ Wk,
                              const float* __restrict__ Wv, const float* __restrict__ Wo)
{
    int idx = blockIdx.x * 256 + threadIdx.x;
    if (idx < 3 * DM * KW) {
        int mat = idx / (DM * KW);
        int rem = idx % (DM * KW);
        int n = rem / KW;
        int kp = rem % KW;
        const float* W = (mat == 0) ? Wq : (mat == 1) ? Wk : Wv;
        unsigned h, l;
        split2(W[(2 * kp) * DM + n], W[(2 * kp + 1) * DM + n], h, l);
        g_WTh[idx] = h;
        g_WTl[idx] = l;
    } else {
        int j = idx - 3 * DM * KW;
        if (j < DM * KW3) {
            int n = j / KW3;
            int kp = j % KW3;
            unsigned h, l;
            split2(Wo[(2 * kp) * DM + n], Wo[(2 * kp + 1) * DM + n], h, l);
            g_WoTh[j] = h;
            g_WoTl[j] = l;
        }
    }
}

// ---------------------------------------------------------------------------
// K0b: H pre-split. One thread = 8 consecutive H columns of one token.
// ---------------------------------------------------------------------------
__global__ void hsplit_kernel(const float* __restrict__ X, const float* __restrict__ STE)
{
    int idx = blockIdx.x * 256 + threadIdx.x;     // exact: NTOK*48 threads
    int tok = idx / 48;
    int q = idx - tok * 48;
    int k0 = q * 8;
    float4 a = ldH(X, STE, tok, k0);
    float4 b = ldH(X, STE, tok, k0 + 4);
    unsigned h0, l0, h1, l1, h2, l2, h3, l3;
    split2(a.x, a.y, h0, l0);
    split2(a.z, a.w, h1, l1);
    split2(b.x, b.y, h2, l2);
    split2(b.z, b.w, h3, l3);
    *(uint4*)(g_Hh + (size_t)tok * KW + q * 4) = make_uint4(h0, h1, h2, h3);
    *(uint4*)(g_Hl + (size_t)tok * KW + q * 4) = make_uint4(l0, l1, l2, l3);
}

// ---------------------------------------------------------------------------
// K1: qkv projection. Block tile 128x128, 8 warps (warp 32x64), K=16/step,
// 24 steps, 4-stage cp.async pipeline, ldmatrix fragment loads.
// ---------------------------------------------------------------------------
__global__ void __launch_bounds__(256, 2)
qkv_kernel(const float* __restrict__ bq, const float* __restrict__ bk,
           const float* __restrict__ bv)
{
    extern __shared__ __align__(16) unsigned dynsmem[];
    const uint32_t sb = (uint32_t)__cvta_generic_to_shared(dynsmem);

    const int mblk = blockIdx.x;
    const int mat  = blockIdx.y;
    const float* bias = (mat == 0) ? bq : (mat == 1) ? bk : bv;
    const unsigned* WTh = g_WTh + (size_t)mat * DM * KW;
    const unsigned* WTl = g_WTl + (size_t)mat * DM * KW;
    unsigned* outh = (mat == 0) ? g_qh : (mat == 1) ? g_kh : g_vh;
    unsigned* outl = (mat == 0) ? g_ql : g_kl;   // only used when mat<2

    const int tid  = threadIdx.x;
    const int lane = tid & 31;
    const int warp = tid >> 5;
    const int wm = warp >> 1;
    const int wn = warp & 1;
    const int lq = lane >> 2;
    const int tq = lane & 3;
    const int m0 = mblk * 128;

    const int ar  = tid >> 1;      // A stage row
    const int ahf = tid & 1;       // A stage k-half
    const int bn  = tid & 127;     // B stage n-row
    const int bhf = tid >> 7;      // B stage k-half

    // staging byte offsets within a stage's array
    const uint32_t aoff = (uint32_t)(ar * PITCH + ahf * 4) * 4;
    const uint32_t boff = (uint32_t)(bn * PITCH + bhf * 4) * 4;
    const unsigned* gAh = g_Hh + (size_t)(m0 + ar) * KW + ahf * 4;
    const unsigned* gAl = g_Hl + (size_t)(m0 + ar) * KW + ahf * 4;
    const unsigned* gBh = WTh + (size_t)bn * KW + bhf * 4;
    const unsigned* gBl = WTl + (size_t)bn * KW + bhf * 4;

    // ldmatrix per-lane byte offsets (within a stage)
    const uint32_t a_ld = (uint32_t)((wm * 32 + (lane & 15)) * PITCH + (lane >> 4) * 4) * 4;
    const int g      = lane >> 3;
    const int b_row  = (g >> 1) * 8 + (lane & 7);
    const int b_word = (g & 1) * 4;

    float acc[2][8][4];
    #pragma unroll
    for (int mt = 0; mt < 2; mt++)
        #pragma unroll
        for (int nt = 0; nt < 8; nt++)
            #pragma unroll
            for (int i = 0; i < 4; i++) acc[mt][nt][i] = 0.f;

    const int NT = KDIM / 16;   // 24

    // prologue: fill the pipeline
    #pragma unroll
    for (int s = 0; s < NSTG; s++) {
        if (s < NT) {
            uint32_t st = sb + s * STG_BYTES;
            CP_ASYNC16(st + A_H_OFF + aoff, gAh + s * 8);
            CP_ASYNC16(st + A_L_OFF + aoff, gAl + s * 8);
            CP_ASYNC16(st + B_H_OFF + boff, gBh + s * 8);
            CP_ASYNC16(st + B_L_OFF + boff, gBl + s * 8);
        }
        CP_COMMIT();
    }

    for (int kt = 0; kt < NT; ++kt) {
        CP_WAIT(NSTG - 1);
        __syncthreads();
        const uint32_t st = sb + (kt & (NSTG - 1)) * STG_BYTES;

        unsigned ah[2][4], al[2][4];
        ldsm_x4(ah[0], st + A_H_OFF + a_ld);
        ldsm_x4(ah[1], st + A_H_OFF + a_ld + 16 * PITCH * 4);
        ldsm_x4(al[0], st + A_L_OFF + a_ld);
        ldsm_x4(al[1], st + A_L_OFF + a_ld + 16 * PITCH * 4);

        unsigned bh[4][4], bl[4][4];
        #pragma unroll
        for (int p = 0; p < 4; p++) {
            uint32_t bo2 = (uint32_t)((wn * 64 + p * 16 + b_row) * PITCH + b_word) * 4;
            ldsm_x4(bh[p], st + B_H_OFF + bo2);
            ldsm_x4(bl[p], st + B_L_OFF + bo2);
        }
        __syncthreads();   // all warps done reading this stage

        if (kt + NSTG < NT) {
            uint32_t sn = sb + ((kt + NSTG) & (NSTG - 1)) * STG_BYTES;
            CP_ASYNC16(sn + A_H_OFF + aoff, gAh + (kt + NSTG) * 8);
            CP_ASYNC16(sn + A_L_OFF + aoff, gAl + (kt + NSTG) * 8);
            CP_ASYNC16(sn + B_H_OFF + boff, gBh + (kt + NSTG) * 8);
            CP_ASYNC16(sn + B_L_OFF + boff, gBl + (kt + NSTG) * 8);
        }
        CP_COMMIT();

        #pragma unroll
        for (int nt = 0; nt < 8; nt++) {
            const unsigned* bhp = &bh[nt >> 1][(nt & 1) * 2];
            const unsigned* blp = &bl[nt >> 1][(nt & 1) * 2];
            #pragma unroll
            for (int mt = 0; mt < 2; mt++) {
                mma16816(acc[mt][nt], ah[mt], bhp);   // hi*hi
                mma16816(acc[mt][nt], al[mt], bhp);   // lo*hi
                mma16816(acc[mt][nt], ah[mt], blp);   // hi*lo
            }
        }
    }

    // epilogue: relu(acc+bias), split bf16 hi/lo, head-major d-pair words
    #pragma unroll
    for (int mt = 0; mt < 2; mt++) {
        int r0 = m0 + wm * 32 + mt * 16 + lq;
        int btk = r0 >> 9;
        int n0  = r0 & 511;
        #pragma unroll
        for (int nt = 0; nt < 8; nt++) {
            int c = wn * 64 + nt * 8 + tq * 2;
            int h = c >> 4, dp = (c & 15) >> 1;
            float b0 = bias[c], b1 = bias[c + 1];
            size_t w0 = ((size_t)(btk * NH + h) * SEQ + n0) * 8 + dp;
            size_t w1 = ((size_t)(btk * NH + h) * SEQ + n0 + 8) * 8 + dp;
            unsigned hw, lw;
            split2(fmaxf(acc[mt][nt][0] + b0, 0.f), fmaxf(acc[mt][nt][1] + b1, 0.f), hw, lw);
            outh[w0] = hw;
            if (mat < 2) outl[w0] = lw;
            split2(fmaxf(acc[mt][nt][2] + b0, 0.f), fmaxf(acc[mt][nt][3] + b1, 0.f), hw, lw);
            outh[w1] = hw;
            if (mat < 2) outl[w1] = lw;
        }
    }
}

// ---------------------------------------------------------------------------
// K2: tensor-core attention (R8 structure + fused ex2 softmax).
// p = 2^(s*log2e/4 - 8*log2e) == exp(s/4 - 8); the constant shift cancels
// in o/L. Scores bounded (relu'd q,k), so no max pass needed.
// ---------------------------------------------------------------------------
__device__ __forceinline__ int sVidx(int d, int kp) {
    return d * 256 + (kp ^ ((d & 7) << 2));
}

__global__ void __launch_bounds__(256, 2)
attn_kernel()
{
    __shared__ unsigned sKh[512 * 8];
    __shared__ unsigned sKl[512 * 8];
    __shared__ unsigned sV[16 * 256];

    const int bth = blockIdx.x;
    const int tid = threadIdx.x;
    const int lane = tid & 31;
    const int warp = tid >> 5;
    const int lq = lane >> 2;
    const int tq = lane & 3;
    const size_t kvbase = (size_t)bth * (SEQ * 8);

    {
        const uint4* gh = (const uint4*)(g_kh + kvbase);
        const uint4* gl = (const uint4*)(g_kl + kvbase);
        uint4* sh = (uint4*)sKh;
        uint4* sl = (uint4*)sKl;
        #pragma unroll
        for (int j = 0; j < 4; j++) {
            sh[tid + j * 256] = gh[tid + j * 256];
            sl[tid + j * 256] = gl[tid + j * 256];
        }
    }
    {
        const uint4* gv = (const uint4*)(g_vh + kvbase);
        int kp = tid;
        uint4 a0 = gv[kp * 4 + 0];
        uint4 a1 = gv[kp * 4 + 1];
        uint4 b0 = gv[kp * 4 + 2];
        uint4 b1 = gv[kp * 4 + 3];
        unsigned ia[8] = {a0.x, a0.y, a0.z, a0.w, a1.x, a1.y, a1.z, a1.w};
        unsigned ib[8] = {b0.x, b0.y, b0.z, b0.w, b1.x, b1.y, b1.z, b1.w};
        #pragma unroll
        for (int dp = 0; dp < 8; dp++) {
            sV[sVidx(2 * dp,     kp)] = prmt(ia[dp], ib[dp], 0x5410);
            sV[sVidx(2 * dp + 1, kp)] = prmt(ia[dp], ib[dp], 0x7632);
        }
    }
    __syncthreads();

    const unsigned* qh = g_qh + kvbase;
    const unsigned* ql = g_ql + kvbase;
    unsigned qah[4][4], qal[4][4];
    #pragma unroll
    for (int mt = 0; mt < 4; mt++) {
        int r = warp * 64 + mt * 16 + lq;
        qah[mt][0] = qh[(size_t)r * 8 + tq];
        qah[mt][1] = qh[(size_t)(r + 8) * 8 + tq];
        qah[mt][2] = qh[(size_t)r * 8 + tq + 4];
        qah[mt][3] = qh[(size_t)(r + 8) * 8 + tq + 4];
        qal[mt][0] = ql[(size_t)r * 8 + tq];
        qal[mt][1] = ql[(size_t)(r + 8) * 8 + tq];
        qal[mt][2] = ql[(size_t)r * 8 + tq + 4];
        qal[mt][3] = ql[(size_t)(r + 8) * 8 + tq + 4];
    }

    float oacc[4][2][4];
    float Lp[4][2];
    #pragma unroll
    for (int mt = 0; mt < 4; mt++) {
        Lp[mt][0] = 0.f; Lp[mt][1] = 0.f;
        #pragma unroll
        for (int nc = 0; nc < 2; nc++)
            #pragma unroll
            for (int i = 0; i < 4; i++) oacc[mt][nc][i] = 0.f;
    }

    for (int c = 0; c < 32; c++) {
        unsigned bh[2][2], bl[2][2], bv[2][2];
        #pragma unroll
        for (int nc = 0; nc < 2; nc++) {
            int kb = c * 16 + nc * 8 + lq;
            bh[nc][0] = sKh[kb * 8 + tq];
            bh[nc][1] = sKh[kb * 8 + tq + 4];
            bl[nc][0] = sKl[kb * 8 + tq];
            bl[nc][1] = sKl[kb * 8 + tq + 4];
            bv[nc][0] = sV[sVidx(nc * 8 + lq, c * 8 + tq)];
            bv[nc][1] = sV[sVidx(nc * 8 + lq, c * 8 + tq + 4)];
        }
        #pragma unroll
        for (int mt = 0; mt < 4; mt++) {
            float s[2][4];
            #pragma unroll
            for (int nc = 0; nc < 2; nc++) {
                #pragma unroll
                for (int i = 0; i < 4; i++) s[nc][i] = 0.f;
                mma16816(s[nc], qah[mt], bh[nc]);
                mma16816(s[nc], qal[mt], bh[nc]);
                mma16816(s[nc], qah[mt], bl[nc]);
                #pragma unroll
                for (int i = 0; i < 4; i++)
                    s[nc][i] = ex2a(fmaf(s[nc][i], EXP_C1, EXP_C2));
            }
            Lp[mt][0] += s[0][0] + s[0][1] + s[1][0] + s[1][1];
            Lp[mt][1] += s[0][2] + s[0][3] + s[1][2] + s[1][3];
            unsigned pA[4] = { packbf(s[0][0], s[0][1]), packbf(s[0][2], s[0][3]),
                               packbf(s[1][0], s[1][1]), packbf(s[1][2], s[1][3]) };
            mma16816(oacc[mt][0], pA, bv[0]);
            mma16816(oacc[mt][1], pA, bv[1]);
        }
    }

    #pragma unroll
    for (int mt = 0; mt < 4; mt++)
        #pragma unroll
        for (int r = 0; r < 2; r++) {
            float v = Lp[mt][r];
            v += __shfl_xor_sync(0xffffffffu, v, 1);
            v += __shfl_xor_sync(0xffffffffu, v, 2);
            Lp[mt][r] = 1.f / v;
        }

    const int btk = bth >> 3;
    const int h   = bth & 7;
    #pragma unroll
    for (int mt = 0; mt < 4; mt++) {
        int r0 = warp * 64 + mt * 16 + lq;
        size_t t0 = ((size_t)(btk * SEQ + r0)) * KW3 + h * 8;
        size_t t1 = ((size_t)(btk * SEQ + r0 + 8)) * KW3 + h * 8;
        #pragma unroll
        for (int nc = 0; nc < 2; nc++) {
            unsigned hw, lw;
            split2(oacc[mt][nc][0] * Lp[mt][0], oacc[mt][nc][1] * Lp[mt][0], hw, lw);
            g_ah[t0 + nc * 4 + tq] = hw;
            g_al[t0 + nc * 4 + tq] = lw;
            split2(oacc[mt][nc][2] * Lp[mt][1], oacc[mt][nc][3] * Lp[mt][1], hw, lw);
            g_ah[t1 + nc * 4 + tq] = hw;
            g_al[t1 + nc * 4 + tq] = lw;
        }
    }
}

// ---------------------------------------------------------------------------
// K3: output projection, same cp.async pipeline as K1 (NT=8).
// ---------------------------------------------------------------------------
__global__ void __launch_bounds__(256, 2)
out_kernel(const float* __restrict__ bo, float* __restrict__ out)
{
    extern __shared__ __align__(16) unsigned dynsmem[];
    const uint32_t sb = (uint32_t)__cvta_generic_to_shared(dynsmem);

    const int mblk = blockIdx.x;
    const int tid  = threadIdx.x;
    const int lane = tid & 31;
    const int warp = tid >> 5;
    const int wm = warp >> 1;
    const int wn = warp & 1;
    const int lq = lane >> 2;
    const int tq = lane & 3;
    const int m0 = mblk * 128;

    const int ar  = tid >> 1;
    const int ahf = tid & 1;
    const int bn  = tid & 127;
    const int bhf = tid >> 7;

    const uint32_t aoff = (uint32_t)(ar * PITCH + ahf * 4) * 4;
    const uint32_t boff = (uint32_t)(bn * PITCH + bhf * 4) * 4;
    const unsigned* gAh = g_ah + (size_t)(m0 + ar) * KW3 + ahf * 4;
    const unsigned* gAl = g_al + (size_t)(m0 + ar) * KW3 + ahf * 4;
    const unsigned* gBh = g_WoTh + (size_t)bn * KW3 + bhf * 4;
    const unsigned* gBl = g_WoTl + (size_t)bn * KW3 + bhf * 4;

    const uint32_t a_ld = (uint32_t)((wm * 32 + (lane & 15)) * PITCH + (lane >> 4) * 4) * 4;
    const int g      = lane >> 3;
    const int b_row  = (g >> 1) * 8 + (lane & 7);
    const int b_word = (g & 1) * 4;

    float acc[2][8][4];
    #pragma unroll
    for (int mt = 0; mt < 2; mt++)
        #pragma unroll
        for (int nt = 0; nt < 8; nt++)
            #pragma unroll
            for (int i = 0; i < 4; i++) acc[mt][nt][i] = 0.f;

    const int NT = DM / 16;   // 8

    #pragma unroll
    for (int s = 0; s < NSTG; s++) {
        if (s < NT) {
            uint32_t st = sb + s * STG_BYTES;
            CP_ASYNC16(st + A_H_OFF + aoff, gAh + s * 8);
            CP_ASYNC16(st + A_L_OFF + aoff, gAl + s * 8);
            CP_ASYNC16(st + B_H_OFF + boff, gBh + s * 8);
            CP_ASYNC16(st + B_L_OFF + boff, gBl + s * 8);
        }
        CP_COMMIT();
    }

    for (int kt = 0; kt < NT; ++kt) {
        CP_WAIT(NSTG - 1);
        __syncthreads();
        const uint32_t st = sb + (kt & (NSTG - 1)) * STG_BYTES;

        unsigned ah[2][4], al[2][4];
        ldsm_x4(ah[0], st + A_H_OFF + a_ld);
        ldsm_x4(ah[1], st + A_H_OFF + a_ld + 16 * PITCH * 4);
        ldsm_x4(al[0], st + A_L_OFF + a_ld);
        ldsm_x4(al[1], st + A_L_OFF + a_ld + 16 * PITCH * 4);

        unsigned bh[4][4], bl[4][4];
        #pragma unroll
        for (int p = 0; p < 4; p++) {
            uint32_t bo2 = (uint32_t)((wn * 64 + p * 16 + b_row) * PITCH + b_word) * 4;
            ldsm_x4(bh[p], st + B_H_OFF + bo2);
            ldsm_x4(bl[p], st + B_L_OFF + bo2);
        }
        __syncthreads();

        if (kt + NSTG < NT) {
            uint32_t sn = sb + ((kt + NSTG) & (NSTG - 1)) * STG_BYTES;
            CP_ASYNC16(sn + A_H_OFF + aoff, gAh + (kt + NSTG) * 8);
            CP_ASYNC16(sn + A_L_OFF + aoff, gAl + (kt + NSTG) * 8);
            CP_ASYNC16(sn + B_H_OFF + boff, gBh + (kt + NSTG) * 8);
            CP_ASYNC16(sn + B_L_OFF + boff, gBl + (kt + NSTG) * 8);
        }
        CP_COMMIT();

        #pragma unroll
        for (int nt = 0; nt < 8; nt++) {
            const unsigned* bhp = &bh[nt >> 1][(nt & 1) * 2];
            const unsigned* blp = &bl[nt >> 1][(nt & 1) * 2];
            #pragma unroll
            for (int mt = 0; mt < 2; mt++) {
                mma16816(acc[mt][nt], ah[mt], bhp);
                mma16816(acc[mt][nt], al[mt], bhp);
                mma16816(acc[mt][nt], ah[mt], blp);
            }
        }
    }

    #pragma unroll
    for (int mt = 0; mt < 2; mt++) {
        int r0 = m0 + wm * 32 + mt * 16 + lq;
        #pragma unroll
        for (int nt = 0; nt < 8; nt++) {
            int c = wn * 64 + nt * 8 + tq * 2;
            float b0 = bo[c], b1 = bo[c + 1];
            float2 v0, v1;
            v0.x = fmaxf(acc[mt][nt][0] + b0, 0.f);
            v0.y = fmaxf(acc[mt][nt][1] + b1, 0.f);
            v1.x = fmaxf(acc[mt][nt][2] + b0, 0.f);
            v1.y = fmaxf(acc[mt][nt][3] + b1, 0.f);
            *(float2*)&out[(size_t)r0 * DM + c]       = v0;
            *(float2*)&out[(size_t)(r0 + 8) * DM + c] = v1;
        }
    }
}

// ---------------------------------------------------------------------------
extern "C" void kernel_launch(void* const* d_in, const int* in_sizes, int n_in,
                              void* d_out, int out_size)
{
    const float* X   = (const float*)d_in[0];
    const float* STE = (const float*)d_in[1];
    const float* Wq  = (const float*)d_in[2];
    const float* bq  = (const float*)d_in[3];
    const float* Wk  = (const float*)d_in[4];
    const float* bk  = (const float*)d_in[5];
    const float* Wv  = (const float*)d_in[6];
    const float* bv  = (const float*)d_in[7];
    const float* Wo  = (const float*)d_in[8];
    const float* bo  = (const float*)d_in[9];
    float* out = (float*)d_out;

    cudaFuncSetAttribute(qkv_kernel, cudaFuncAttributeMaxDynamicSharedMemorySize, GEMM_SMEM);
    cudaFuncSetAttribute(out_kernel, cudaFuncAttributeMaxDynamicSharedMemorySize, GEMM_SMEM);

    wsplit_kernel<<<(3 * DM * KW + DM * KW3 + 255) / 256, 256>>>(Wq, Wk, Wv, Wo);
    hsplit_kernel<<<NTOK * 48 / 256, 256>>>(X, STE);
    qkv_kernel<<<dim3(NTOK / 128, 3), 256, GEMM_SMEM>>>(bq, bk, bv);
    attn_kernel<<<BT * NH, 256>>>();
    out_kernel<<<NTOK / 128, 256, GEMM_SMEM>>>(bo, out);
}